// round 1
// baseline (speedup 1.0000x reference)
#include <cuda_runtime.h>
#include <math.h>

// ---------------- problem constants ----------------
#define N_     2
#define H_     240
#define W_     320
#define HW     76800          // H_*W_
#define C_     128
#define HEADS_ 4
#define HD_    32
#define WS_    7
#define DEPTH_ 4
#define HID_   512
#define NWH_   35             // ceil(240/7) -> padded 245
#define NWW_   46             // ceil(320/7) -> padded 322
#define NWIN_  (N_*NWH_*NWW_) // 3220
#define WT_    49
#define TOKW_  (NWIN_*WT_)    // 157780
#define NQ_    128
#define DOUT_  256

// ---------------- scratch (device globals; no allocs allowed) ----------------
__device__ float g_xt    [(size_t)N_*HW*C_];     // x transposed to (n, p, c)
__device__ float g_tok0  [(size_t)N_*HW*C_];     // conv output (kept for maps)
__device__ float g_tokens[(size_t)N_*HW*C_];     // running tokens
__device__ float g_h     [(size_t)TOKW_*C_];     // windowed LN out / proj out
__device__ float g_qkv   [(size_t)TOKW_*3*C_];   // qkv
__device__ float g_attno [(size_t)TOKW_*C_];     // attn out / LN2 out
__device__ float g_mlp1  [(size_t)N_*HW*HID_];   // fc1 out
__device__ float g_head  [N_*C_];

// ---------------- helpers ----------------
__device__ __forceinline__ float warp_sum(float v) {
    #pragma unroll
    for (int o = 16; o; o >>= 1) v += __shfl_xor_sync(0xffffffffu, v, o);
    return v;
}
__device__ __forceinline__ float warp_max(float v) {
    #pragma unroll
    for (int o = 16; o; o >>= 1) v = fmaxf(v, __shfl_xor_sync(0xffffffffu, v, o));
    return v;
}
__device__ __forceinline__ float gelu_exact(float x) {
    return 0.5f * x * (1.0f + erff(x * 0.70710678118654752f));
}

// ---------------- transpose (n,c,p) -> (n,p,c) ----------------
__global__ void transpose_ncp(const float* __restrict__ in, float* __restrict__ out) {
    __shared__ float tile[32][33];
    int n = blockIdx.z;
    int p0 = blockIdx.x * 32, c0 = blockIdx.y * 32;
    int x = threadIdx.x, y = threadIdx.y; // 32x8
    const float* src = in + (size_t)n * C_ * HW;
    #pragma unroll
    for (int yy = y; yy < 32; yy += 8)
        tile[yy][x] = src[(size_t)(c0 + yy) * HW + p0 + x];
    __syncthreads();
    float* dst = out + (size_t)n * HW * C_;
    #pragma unroll
    for (int yy = y; yy < 32; yy += 8)
        dst[(size_t)(p0 + yy) * C_ + c0 + x] = tile[x][yy];
}

// ---------------- flat copy ----------------
__global__ void copy_f4(const float4* __restrict__ src, float4* __restrict__ dst, int n4) {
    int i = blockIdx.x * blockDim.x + threadIdx.x;
    if (i < n4) dst[i] = src[i];
}

// ---------------- tiled SGEMM: out[M,N] = A[M,K] . B[N,K]^T + bias ----------------
// EPI: 0 = store, 1 = gelu+store, 2 = accumulate into out (residual)
template <int EPI>
__global__ __launch_bounds__(256)
void sgemm128(const float* __restrict__ A, const float* __restrict__ B,
              const float* __restrict__ bias, float* __restrict__ Cc,
              int M, int N, int K) {
    __shared__ float As[16][128];
    __shared__ float Bs[16][128];
    int tid = threadIdx.x;
    int tx = tid & 15, ty = tid >> 4;
    int tileN = blockIdx.x * 128, tileM = blockIdx.y * 128;

    float acc[8][8];
    #pragma unroll
    for (int i = 0; i < 8; i++)
        #pragma unroll
        for (int j = 0; j < 8; j++) acc[i][j] = 0.f;

    for (int k0 = 0; k0 < K; k0 += 16) {
        #pragma unroll
        for (int l = 0; l < 2; l++) {
            int flat = tid + l * 256;   // 0..511 float4 slots
            int r  = flat >> 2;         // 0..127
            int kq = (flat & 3) * 4;    // 0,4,8,12
            int gm = tileM + r;
            float4 va = make_float4(0.f, 0.f, 0.f, 0.f);
            if (gm < M) va = *(const float4*)(A + (size_t)gm * K + k0 + kq);
            As[kq + 0][r] = va.x; As[kq + 1][r] = va.y;
            As[kq + 2][r] = va.z; As[kq + 3][r] = va.w;
            int gn = tileN + r;
            float4 vb = make_float4(0.f, 0.f, 0.f, 0.f);
            if (gn < N) vb = *(const float4*)(B + (size_t)gn * K + k0 + kq);
            Bs[kq + 0][r] = vb.x; Bs[kq + 1][r] = vb.y;
            Bs[kq + 2][r] = vb.z; Bs[kq + 3][r] = vb.w;
        }
        __syncthreads();
        #pragma unroll
        for (int k = 0; k < 16; k++) {
            float a[8], b[8];
            float4 a0 = *(const float4*)&As[k][ty * 8];
            float4 a1 = *(const float4*)&As[k][ty * 8 + 4];
            float4 b0 = *(const float4*)&Bs[k][tx * 8];
            float4 b1 = *(const float4*)&Bs[k][tx * 8 + 4];
            a[0]=a0.x;a[1]=a0.y;a[2]=a0.z;a[3]=a0.w;a[4]=a1.x;a[5]=a1.y;a[6]=a1.z;a[7]=a1.w;
            b[0]=b0.x;b[1]=b0.y;b[2]=b0.z;b[3]=b0.w;b[4]=b1.x;b[5]=b1.y;b[6]=b1.z;b[7]=b1.w;
            #pragma unroll
            for (int i = 0; i < 8; i++)
                #pragma unroll
                for (int j = 0; j < 8; j++)
                    acc[i][j] = fmaf(a[i], b[j], acc[i][j]);
        }
        __syncthreads();
    }

    #pragma unroll
    for (int i = 0; i < 8; i++) {
        int gm = tileM + ty * 8 + i;
        if (gm >= M) continue;
        #pragma unroll
        for (int j = 0; j < 8; j++) {
            int gn = tileN + tx * 8 + j;
            if (gn >= N) continue;
            float v = acc[i][j] + (bias ? bias[gn] : 0.f);
            size_t oi = (size_t)gm * N + gn;
            if (EPI == 0)      Cc[oi] = v;
            else if (EPI == 1) Cc[oi] = gelu_exact(v);
            else               Cc[oi] += v;
        }
    }
}

// ---------------- LN over C=128, gathered into padded window layout ----------------
__global__ void ln_window(const float* __restrict__ tokens,
                          const float* __restrict__ g, const float* __restrict__ b,
                          float* __restrict__ out) {
    int warp = (blockIdx.x * blockDim.x + threadIdx.x) >> 5;
    int lane = threadIdx.x & 31;
    if (warp >= TOKW_) return;
    int w = warp / WT_, i = warp % WT_;
    int n = w / (NWH_ * NWW_); int rem = w % (NWH_ * NWW_);
    int wh = rem / NWW_, ww = rem % NWW_;
    int hp = wh * WS_ + i / WS_;
    int wp = ww * WS_ + i % WS_;
    float* orow = out + (size_t)warp * C_;
    if (hp < H_ && wp < W_) {
        const float* irow = tokens + ((size_t)n * HW + hp * W_ + wp) * C_;
        float v[4];
        #pragma unroll
        for (int j = 0; j < 4; j++) v[j] = irow[lane + 32 * j];
        float mu = warp_sum(v[0] + v[1] + v[2] + v[3]) * (1.f / C_);
        float vs = 0.f;
        #pragma unroll
        for (int j = 0; j < 4; j++) { float d = v[j] - mu; vs += d * d; }
        vs = warp_sum(vs) * (1.f / C_);
        float rstd = rsqrtf(vs + 1e-5f);
        #pragma unroll
        for (int j = 0; j < 4; j++) {
            int c = lane + 32 * j;
            orow[c] = (v[j] - mu) * rstd * g[c] + b[c];
        }
    } else {
        #pragma unroll
        for (int j = 0; j < 4; j++) orow[lane + 32 * j] = 0.f;
    }
}

// ---------------- plain LN over rows ----------------
__global__ void ln_rows(const float* __restrict__ in,
                        const float* __restrict__ g, const float* __restrict__ b,
                        float* __restrict__ out, int rows) {
    int warp = (blockIdx.x * blockDim.x + threadIdx.x) >> 5;
    int lane = threadIdx.x & 31;
    if (warp >= rows) return;
    const float* irow = in + (size_t)warp * C_;
    float v[4];
    #pragma unroll
    for (int j = 0; j < 4; j++) v[j] = irow[lane + 32 * j];
    float mu = warp_sum(v[0] + v[1] + v[2] + v[3]) * (1.f / C_);
    float vs = 0.f;
    #pragma unroll
    for (int j = 0; j < 4; j++) { float d = v[j] - mu; vs += d * d; }
    vs = warp_sum(vs) * (1.f / C_);
    float rstd = rsqrtf(vs + 1e-5f);
    float* orow = out + (size_t)warp * C_;
    #pragma unroll
    for (int j = 0; j < 4; j++) {
        int c = lane + 32 * j;
        orow[c] = (v[j] - mu) * rstd * g[c] + b[c];
    }
}

// ---------------- attention: one block per (window, head) ----------------
__global__ __launch_bounds__(256)
void attn_win(const float* __restrict__ qkv, float* __restrict__ out) {
    __shared__ float qs[WT_ * HD_];
    __shared__ float ks[WT_ * HD_];
    __shared__ float vs[WT_ * HD_];
    __shared__ float lg[WT_ * WT_];
    int w = blockIdx.x >> 2;
    int head = blockIdx.x & 3;
    int tid = threadIdx.x;

    for (int idx = tid; idx < WT_ * HD_; idx += 256) {
        int i = idx / HD_, dd = idx % HD_;
        const float* base = qkv + (size_t)(w * WT_ + i) * (3 * C_) + head * HD_ + dd;
        qs[idx] = base[0];
        ks[idx] = base[C_];
        vs[idx] = base[2 * C_];
    }
    __syncthreads();

    const float scale = 0.17677669529663687f; // 32^-0.5
    for (int idx = tid; idx < WT_ * WT_; idx += 256) {
        int i = idx / WT_, j = idx % WT_;
        float s = 0.f;
        #pragma unroll
        for (int d = 0; d < HD_; d++) s = fmaf(qs[i * HD_ + d], ks[j * HD_ + d], s);
        lg[idx] = s * scale;
    }
    __syncthreads();

    int warp = tid >> 5, lane = tid & 31;
    for (int r = warp; r < WT_; r += 8) {
        float m = -1e30f;
        for (int j = lane; j < WT_; j += 32) m = fmaxf(m, lg[r * WT_ + j]);
        m = warp_max(m);
        float s = 0.f;
        for (int j = lane; j < WT_; j += 32) {
            float e = __expf(lg[r * WT_ + j] - m);
            lg[r * WT_ + j] = e;
            s += e;
        }
        s = warp_sum(s);
        float inv = 1.f / s;
        for (int j = lane; j < WT_; j += 32) lg[r * WT_ + j] *= inv;
    }
    __syncthreads();

    for (int idx = tid; idx < WT_ * HD_; idx += 256) {
        int i = idx / HD_, dd = idx % HD_;
        float s = 0.f;
        #pragma unroll
        for (int j = 0; j < WT_; j++) s = fmaf(lg[i * WT_ + j], vs[j * HD_ + dd], s);
        out[(size_t)(w * WT_ + i) * C_ + head * HD_ + dd] = s;
    }
}

// ---------------- residual: tokens += windowed proj output (valid positions) ----------------
__global__ void add_windows(float* __restrict__ tokens, const float* __restrict__ src) {
    int idx = blockIdx.x * blockDim.x + threadIdx.x;
    if (idx >= N_ * HW * C_) return;
    int c = idx & (C_ - 1);
    int row = idx >> 7;
    int n = row / HW, p = row % HW;
    int h = p / W_, w = p % W_;
    int t = ((n * NWH_ + h / WS_) * NWW_ + w / WS_) * WT_ + (h % WS_) * WS_ + (w % WS_);
    tokens[idx] += src[(size_t)t * C_ + c];
}

// ---------------- head mean reduce ----------------
__global__ void zero_head() { if (threadIdx.x < N_ * C_) g_head[threadIdx.x] = 0.f; }

__global__ void head_reduce(const float* __restrict__ tokens) {
    int n = blockIdx.x / (HW / 128);
    int pb = (blockIdx.x % (HW / 128)) * 128;
    int c = threadIdx.x;
    float s = 0.f;
    for (int i = 0; i < 128; i++) s += tokens[((size_t)n * HW + pb + i) * C_ + c];
    atomicAdd(&g_head[n * C_ + c], s);
}

// ---------------- tiny output MLP (y) ----------------
__global__ void head_mlp(const float* __restrict__ r1w, const float* __restrict__ r1b,
                         const float* __restrict__ r2w, const float* __restrict__ r2b,
                         const float* __restrict__ r3w, const float* __restrict__ r3b,
                         float* __restrict__ out) {
    __shared__ float hh[N_ * C_];
    __shared__ float y1[N_ * 256];
    __shared__ float y2[N_ * 256];
    __shared__ float y3[N_ * DOUT_];
    __shared__ float ssum[N_];
    int tid = threadIdx.x;
    if (tid < N_ * C_) hh[tid] = g_head[tid] * (1.f / HW);
    __syncthreads();
    for (int o = tid; o < N_ * 256; o += 256) {
        int n = o >> 8, j = o & 255;
        float s = r1b[j];
        for (int c = 0; c < C_; c++) s = fmaf(hh[n * C_ + c], r1w[j * C_ + c], s);
        y1[o] = s > 0.f ? s : 0.01f * s;
    }
    __syncthreads();
    for (int o = tid; o < N_ * 256; o += 256) {
        int n = o >> 8, j = o & 255;
        float s = r2b[j];
        for (int c = 0; c < 256; c++) s = fmaf(y1[n * 256 + c], r2w[j * 256 + c], s);
        y2[o] = s > 0.f ? s : 0.01f * s;
    }
    __syncthreads();
    for (int o = tid; o < N_ * DOUT_; o += 256) {
        int n = o >> 8, j = o & 255;
        float s = r3b[j];
        for (int c = 0; c < 256; c++) s = fmaf(y2[n * 256 + c], r3w[j * 256 + c], s);
        y3[o] = fmaxf(s, 0.f) + 0.1f;
    }
    __syncthreads();
    if (tid < N_) {
        float s = 0.f;
        for (int j = 0; j < DOUT_; j++) s += y3[tid * DOUT_ + j];
        ssum[tid] = s;
    }
    __syncthreads();
    for (int o = tid; o < N_ * DOUT_; o += 256) {
        int n = o >> 8;
        out[o] = y3[o] / ssum[n];
    }
}

// ---------------- host launch ----------------
static float* symaddr(const void* sym) {
    void* p = nullptr;
    cudaGetSymbolAddress(&p, sym);
    return (float*)p;
}

extern "C" void kernel_launch(void* const* d_in, const int* in_sizes, int n_in,
                              void* d_out, int out_size) {
    const float* x      = (const float*)d_in[0];
    const float* conv_w = (const float*)d_in[1];
    const float* conv_b = (const float*)d_in[2];
    const float* n1_g   = (const float*)d_in[3];
    const float* n1_b   = (const float*)d_in[4];
    const float* qkv_w  = (const float*)d_in[5];
    const float* qkv_b  = (const float*)d_in[6];
    const float* proj_w = (const float*)d_in[7];
    const float* proj_b = (const float*)d_in[8];
    const float* n2_g   = (const float*)d_in[9];
    const float* n2_b   = (const float*)d_in[10];
    const float* fc1_w  = (const float*)d_in[11];
    const float* fc1_b  = (const float*)d_in[12];
    const float* fc2_w  = (const float*)d_in[13];
    const float* fc2_b  = (const float*)d_in[14];
    const float* r1_w   = (const float*)d_in[15];
    const float* r1_b   = (const float*)d_in[16];
    const float* r2_w   = (const float*)d_in[17];
    const float* r2_b   = (const float*)d_in[18];
    const float* r3_w   = (const float*)d_in[19];
    const float* r3_b   = (const float*)d_in[20];
    float* out = (float*)d_out;

    float* xt     = symaddr(g_xt);
    float* tok0   = symaddr(g_tok0);
    float* tokens = symaddr(g_tokens);
    float* hbuf   = symaddr(g_h);
    float* qkvb   = symaddr(g_qkv);
    float* attno  = symaddr(g_attno);
    float* mlp1   = symaddr(g_mlp1);

    // 1) transpose x (n,c,p) -> (n,p,c)
    transpose_ncp<<<dim3(HW / 32, C_ / 32, N_), dim3(32, 8)>>>(x, xt);

    // 2) 1x1 conv as GEMM per image
    for (int n = 0; n < N_; n++) {
        sgemm128<0><<<dim3(1, HW / 128), 256>>>(
            xt + (size_t)n * HW * C_, conv_w, conv_b,
            tokens + (size_t)n * HW * C_, HW, C_, C_);
    }
    // keep conv output for maps
    copy_f4<<<(N_ * HW * C_ / 4 + 255) / 256, 256>>>((const float4*)tokens, (float4*)tok0,
                                                     N_ * HW * C_ / 4);

    int lnw_blocks = (TOKW_ + 7) / 8;
    int lnr_blocks = (N_ * HW + 7) / 8;
    int mTiles_w = (TOKW_ + 127) / 128;

    for (int d = 0; d < DEPTH_; d++) {
        // LN1 + window gather (+ zero pad)
        ln_window<<<lnw_blocks, 256>>>(tokens, n1_g + d * C_, n1_b + d * C_, hbuf);
        // qkv
        sgemm128<0><<<dim3(3, mTiles_w), 256>>>(
            hbuf, qkv_w + (size_t)d * 3 * C_ * C_, qkv_b + d * 3 * C_,
            qkvb, TOKW_, 3 * C_, C_);
        // attention
        attn_win<<<NWIN_ * HEADS_, 256>>>(qkvb, attno);
        // proj
        sgemm128<0><<<dim3(1, mTiles_w), 256>>>(
            attno, proj_w + (size_t)d * C_ * C_, proj_b + d * C_,
            hbuf, TOKW_, C_, C_);
        // residual add (window scatter)
        add_windows<<<N_ * HW * C_ / 256, 256>>>(tokens, hbuf);
        // LN2
        ln_rows<<<lnr_blocks, 256>>>(tokens, n2_g + d * C_, n2_b + d * C_, attno, N_ * HW);
        // fc1 + gelu
        sgemm128<1><<<dim3(HID_ / 128, N_ * HW / 128), 256>>>(
            attno, fc1_w + (size_t)d * HID_ * C_, fc1_b + d * HID_,
            mlp1, N_ * HW, HID_, C_);
        // fc2, accumulate into tokens (residual)
        sgemm128<2><<<dim3(1, N_ * HW / 128), 256>>>(
            mlp1, fc2_w + (size_t)d * C_ * HID_, fc2_b + d * C_,
            tokens, N_ * HW, C_, HID_);
    }

    // head mean + tiny MLP -> y (first 512 floats of out)
    zero_head<<<1, 256>>>();
    head_reduce<<<N_ * (HW / 128), 128>>>(tokens);
    head_mlp<<<1, 256>>>(r1_w, r1_b, r2_w, r2_b, r3_w, r3_b, out);

    // maps: out[n,q,p] = queries[n,q,:] . tok0[n,p,:]
    for (int n = 0; n < N_; n++) {
        sgemm128<0><<<dim3(HW / 128, 1), 256>>>(
            tokens + (size_t)n * HW * C_,   // first NQ rows are the queries
            tok0 + (size_t)n * HW * C_,
            nullptr,
            out + 512 + (size_t)n * NQ_ * HW,
            NQ_, HW, C_);
    }
}

// round 3
// speedup vs baseline: 1.7908x; 1.7908x over previous
#include <cuda_runtime.h>
#include <cuda_fp16.h>
#include <cstdint>
#include <math.h>

// ---------------- problem constants ----------------
#define N_     2
#define H_     240
#define W_     320
#define HW     76800          // H_*W_
#define C_     128
#define HEADS_ 4
#define HD_    32
#define WS_    7
#define DEPTH_ 4
#define HID_   512
#define NWH_   35
#define NWW_   46
#define NWIN_  (N_*NWH_*NWW_) // 3220
#define WT_    49
#define TOKW_  (NWIN_*WT_)    // 157780
#define NQ_    128
#define DOUT_  256

// ---------------- scratch (device globals; no allocs allowed) ----------------
__device__ float g_xt    [(size_t)N_*HW*C_];
__device__ float g_tok0  [(size_t)N_*HW*C_];
__device__ float g_tokens[(size_t)N_*HW*C_];
__device__ float g_h     [(size_t)TOKW_*C_];
__device__ float g_qkv   [(size_t)TOKW_*3*C_];
__device__ float g_attno [(size_t)TOKW_*C_];
__device__ float g_mlp1  [(size_t)N_*HW*HID_];
__device__ float g_head  [N_*C_];

// ---------------- helpers ----------------
__device__ __forceinline__ uint32_t smem_u32(const void* p) {
    uint32_t a;
    asm("{ .reg .u64 t; cvta.to.shared.u64 t, %1; cvt.u32.u64 %0, t; }" : "=r"(a) : "l"(p));
    return a;
}
__device__ __forceinline__ float warp_sum(float v) {
    #pragma unroll
    for (int o = 16; o; o >>= 1) v += __shfl_xor_sync(0xffffffffu, v, o);
    return v;
}
__device__ __forceinline__ float warp_max(float v) {
    #pragma unroll
    for (int o = 16; o; o >>= 1) v = fmaxf(v, __shfl_xor_sync(0xffffffffu, v, o));
    return v;
}
__device__ __forceinline__ float gelu_exact(float x) {
    return 0.5f * x * (1.0f + erff(x * 0.70710678118654752f));
}
__device__ __forceinline__ void ldsm_x4(uint32_t& r0, uint32_t& r1, uint32_t& r2, uint32_t& r3,
                                        uint32_t addr) {
    asm volatile("ldmatrix.sync.aligned.m8n8.x4.shared.b16 {%0,%1,%2,%3}, [%4];"
                 : "=r"(r0), "=r"(r1), "=r"(r2), "=r"(r3) : "r"(addr));
}
__device__ __forceinline__ void mma16816(float* c, const uint32_t* a, const uint32_t* b) {
    asm volatile(
        "mma.sync.aligned.m16n8k16.row.col.f32.f16.f16.f32 "
        "{%0,%1,%2,%3}, {%4,%5,%6,%7}, {%8,%9}, {%0,%1,%2,%3};"
        : "+f"(c[0]), "+f"(c[1]), "+f"(c[2]), "+f"(c[3])
        : "r"(a[0]), "r"(a[1]), "r"(a[2]), "r"(a[3]), "r"(b[0]), "r"(b[1]));
}
__device__ __forceinline__ uint4 cvt8_guard(const float* p, bool ok) {
    uint4 u = make_uint4(0u, 0u, 0u, 0u);
    if (ok) {
        float4 f0 = *(const float4*)p;
        float4 f1 = *(const float4*)(p + 4);
        __half2 h0 = __floats2half2_rn(f0.x, f0.y);
        __half2 h1 = __floats2half2_rn(f0.z, f0.w);
        __half2 h2 = __floats2half2_rn(f1.x, f1.y);
        __half2 h3 = __floats2half2_rn(f1.z, f1.w);
        u.x = *(uint32_t*)&h0; u.y = *(uint32_t*)&h1;
        u.z = *(uint32_t*)&h2; u.w = *(uint32_t*)&h3;
    }
    return u;
}

// ================= fp16 mma.sync GEMM: C[M,N] = A[M,K] . B[N,K]^T (+bias) =================
// EPI: 0 store, 1 gelu+store, 2 accumulate (residual), 3 dual store
// Tile 128x128, BK=32 double-buffered, 256 threads (8 warps, 2x4 warp grid, 64x32 warp tile).
#define RS_ 40   // smem row stride in halves (80 bytes): conflict-free ldmatrix

template <int EPI>
__global__ __launch_bounds__(256)
void gemm_mma(const float* __restrict__ A, const float* __restrict__ B,
              const float* __restrict__ bias, float* __restrict__ Cc,
              float* __restrict__ C2, int M, int N, int K) {
    __shared__ __align__(16) __half As[2][128 * RS_];
    __shared__ __align__(16) __half Bs[2][128 * RS_];

    const int tid = threadIdx.x;
    const int wid = tid >> 5, lane = tid & 31;
    const int tileN = blockIdx.x * 128, tileM = blockIdx.y * 128;
    const int wm = (wid >> 2) * 64, wn = (wid & 3) * 32;
    const int rr = lane & 7, gg = lane >> 3;

    const uint32_t sA = smem_u32(As), sB = smem_u32(Bs);
    const int ldr = tid >> 2;            // load row 0..63? no: flat>>2 below
    (void)ldr;

    float acc[4][4][4];
    #pragma unroll
    for (int i = 0; i < 4; i++)
        #pragma unroll
        for (int j = 0; j < 4; j++)
            #pragma unroll
            for (int k = 0; k < 4; k++) acc[i][j][k] = 0.f;

    const int KC = K >> 5;

    // prologue: chunk 0 straight to smem
    #pragma unroll
    for (int q = 0; q < 2; q++) {
        int flat = tid + q * 256;
        int r = flat >> 2, c8 = (flat & 3) * 8;
        uint4 ua = cvt8_guard(A + (size_t)(tileM + r) * K + c8, tileM + r < M);
        *(uint4*)&As[0][r * RS_ + c8] = ua;
        uint4 ub = cvt8_guard(B + (size_t)(tileN + r) * K + c8, tileN + r < N);
        *(uint4*)&Bs[0][r * RS_ + c8] = ub;
    }
    __syncthreads();

    for (int kc = 0; kc < KC; kc++) {
        const int cur = kc & 1;
        uint4 stA[2], stB[2];
        const bool more = (kc + 1 < KC);
        if (more) {
            int kbase = (kc + 1) * 32;
            #pragma unroll
            for (int q = 0; q < 2; q++) {
                int flat = tid + q * 256;
                int r = flat >> 2, c8 = (flat & 3) * 8;
                stA[q] = cvt8_guard(A + (size_t)(tileM + r) * K + kbase + c8, tileM + r < M);
                stB[q] = cvt8_guard(B + (size_t)(tileN + r) * K + kbase + c8, tileN + r < N);
            }
        }

        // compute current chunk: 2 x k16 steps
        const uint32_t aBase = sA + cur * (128 * RS_ * 2);
        const uint32_t bBase = sB + cur * (128 * RS_ * 2);
        #pragma unroll
        for (int ks = 0; ks < 2; ks++) {
            uint32_t a[4][4];
            #pragma unroll
            for (int mi = 0; mi < 4; mi++) {
                int row = wm + mi * 16 + rr + ((gg & 1) << 3);
                int col = ks * 16 + ((gg >> 1) << 3);
                ldsm_x4(a[mi][0], a[mi][1], a[mi][2], a[mi][3],
                        aBase + (uint32_t)(row * RS_ + col) * 2);
            }
            uint32_t b[2][4];
            #pragma unroll
            for (int p = 0; p < 2; p++) {
                int row = wn + p * 16 + rr + ((gg & 1) << 3);
                int col = ks * 16 + ((gg >> 1) << 3);
                ldsm_x4(b[p][0], b[p][1], b[p][2], b[p][3],
                        bBase + (uint32_t)(row * RS_ + col) * 2);
            }
            #pragma unroll
            for (int mi = 0; mi < 4; mi++) {
                #pragma unroll
                for (int nj = 0; nj < 4; nj++) {
                    int p = nj >> 1;
                    uint32_t bb[2];
                    if (nj & 1) { bb[0] = b[p][1]; bb[1] = b[p][3]; }
                    else        { bb[0] = b[p][0]; bb[1] = b[p][2]; }
                    mma16816(acc[mi][nj], a[mi], bb);
                }
            }
        }

        if (more) {
            int nb = cur ^ 1;
            #pragma unroll
            for (int q = 0; q < 2; q++) {
                int flat = tid + q * 256;
                int r = flat >> 2, c8 = (flat & 3) * 8;
                *(uint4*)&As[nb][r * RS_ + c8] = stA[q];
                *(uint4*)&Bs[nb][r * RS_ + c8] = stB[q];
            }
            __syncthreads();
        }
    }

    // epilogue: direct register -> global
    const int er = lane >> 2, ec = (lane & 3) * 2;
    #pragma unroll
    for (int mi = 0; mi < 4; mi++) {
        #pragma unroll
        for (int half = 0; half < 2; half++) {
            int gm = tileM + wm + mi * 16 + er + half * 8;
            if (gm >= M) continue;
            #pragma unroll
            for (int nj = 0; nj < 4; nj++) {
                int gn = tileN + wn + nj * 8 + ec;
                float vx = acc[mi][nj][half * 2 + 0];
                float vy = acc[mi][nj][half * 2 + 1];
                if (bias) { vx += bias[gn]; vy += bias[gn + 1]; }
                if (EPI == 1) { vx = gelu_exact(vx); vy = gelu_exact(vy); }
                size_t o = (size_t)gm * N + gn;
                if (EPI == 2) {
                    float2 old = *(float2*)(Cc + o);
                    vx += old.x; vy += old.y;
                    *(float2*)(Cc + o) = make_float2(vx, vy);
                } else {
                    *(float2*)(Cc + o) = make_float2(vx, vy);
                    if (EPI == 3) *(float2*)(C2 + o) = make_float2(vx, vy);
                }
            }
        }
    }
}

// ---------------- transpose (n,c,p) -> (n,p,c) ----------------
__global__ void transpose_ncp(const float* __restrict__ in, float* __restrict__ out) {
    __shared__ float tile[32][33];
    int n = blockIdx.z;
    int p0 = blockIdx.x * 32, c0 = blockIdx.y * 32;
    int x = threadIdx.x, y = threadIdx.y;
    const float* src = in + (size_t)n * C_ * HW;
    #pragma unroll
    for (int yy = y; yy < 32; yy += 8)
        tile[yy][x] = src[(size_t)(c0 + yy) * HW + p0 + x];
    __syncthreads();
    float* dst = out + (size_t)n * HW * C_;
    #pragma unroll
    for (int yy = y; yy < 32; yy += 8)
        dst[(size_t)(p0 + yy) * C_ + c0 + x] = tile[x][yy];
}

// ---------------- LN over C=128, gathered into padded window layout ----------------
__global__ void ln_window(const float* __restrict__ tokens,
                          const float* __restrict__ g, const float* __restrict__ b,
                          float* __restrict__ out) {
    int warp = (blockIdx.x * blockDim.x + threadIdx.x) >> 5;
    int lane = threadIdx.x & 31;
    if (warp >= TOKW_) return;
    int w = warp / WT_, i = warp % WT_;
    int n = w / (NWH_ * NWW_); int rem = w % (NWH_ * NWW_);
    int wh = rem / NWW_, ww = rem % NWW_;
    int hp = wh * WS_ + i / WS_;
    int wp = ww * WS_ + i % WS_;
    float* orow = out + (size_t)warp * C_;
    if (hp < H_ && wp < W_) {
        const float* irow = tokens + ((size_t)n * HW + hp * W_ + wp) * C_;
        float v[4];
        #pragma unroll
        for (int j = 0; j < 4; j++) v[j] = irow[lane + 32 * j];
        float mu = warp_sum(v[0] + v[1] + v[2] + v[3]) * (1.f / C_);
        float vs = 0.f;
        #pragma unroll
        for (int j = 0; j < 4; j++) { float d = v[j] - mu; vs += d * d; }
        vs = warp_sum(vs) * (1.f / C_);
        float rstd = rsqrtf(vs + 1e-5f);
        #pragma unroll
        for (int j = 0; j < 4; j++) {
            int c = lane + 32 * j;
            orow[c] = (v[j] - mu) * rstd * g[c] + b[c];
        }
    } else {
        #pragma unroll
        for (int j = 0; j < 4; j++) orow[lane + 32 * j] = 0.f;
    }
}

// ---------------- plain LN over rows ----------------
__global__ void ln_rows(const float* __restrict__ in,
                        const float* __restrict__ g, const float* __restrict__ b,
                        float* __restrict__ out, int rows) {
    int warp = (blockIdx.x * blockDim.x + threadIdx.x) >> 5;
    int lane = threadIdx.x & 31;
    if (warp >= rows) return;
    const float* irow = in + (size_t)warp * C_;
    float v[4];
    #pragma unroll
    for (int j = 0; j < 4; j++) v[j] = irow[lane + 32 * j];
    float mu = warp_sum(v[0] + v[1] + v[2] + v[3]) * (1.f / C_);
    float vs = 0.f;
    #pragma unroll
    for (int j = 0; j < 4; j++) { float d = v[j] - mu; vs += d * d; }
    vs = warp_sum(vs) * (1.f / C_);
    float rstd = rsqrtf(vs + 1e-5f);
    float* orow = out + (size_t)warp * C_;
    #pragma unroll
    for (int j = 0; j < 4; j++) {
        int c = lane + 32 * j;
        orow[c] = (v[j] - mu) * rstd * g[c] + b[c];
    }
}

// ---------------- attention: one block per (window, head) ----------------
__global__ __launch_bounds__(256)
void attn_win(const float* __restrict__ qkv, float* __restrict__ out) {
    __shared__ float qs[WT_ * HD_];
    __shared__ float ks[WT_ * HD_];
    __shared__ float vs[WT_ * HD_];
    __shared__ float lg[WT_ * WT_];
    int w = blockIdx.x >> 2;
    int head = blockIdx.x & 3;
    int tid = threadIdx.x;

    for (int idx = tid; idx < WT_ * HD_; idx += 256) {
        int i = idx / HD_, dd = idx % HD_;
        const float* base = qkv + (size_t)(w * WT_ + i) * (3 * C_) + head * HD_ + dd;
        qs[idx] = base[0];
        ks[idx] = base[C_];
        vs[idx] = base[2 * C_];
    }
    __syncthreads();

    const float scale = 0.17677669529663687f;
    for (int idx = tid; idx < WT_ * WT_; idx += 256) {
        int i = idx / WT_, j = idx % WT_;
        float s = 0.f;
        #pragma unroll
        for (int d = 0; d < HD_; d++) s = fmaf(qs[i * HD_ + d], ks[j * HD_ + d], s);
        lg[idx] = s * scale;
    }
    __syncthreads();

    int warp = tid >> 5, lane = tid & 31;
    for (int r = warp; r < WT_; r += 8) {
        float m = -1e30f;
        for (int j = lane; j < WT_; j += 32) m = fmaxf(m, lg[r * WT_ + j]);
        m = warp_max(m);
        float s = 0.f;
        for (int j = lane; j < WT_; j += 32) {
            float e = __expf(lg[r * WT_ + j] - m);
            lg[r * WT_ + j] = e;
            s += e;
        }
        s = warp_sum(s);
        float inv = 1.f / s;
        for (int j = lane; j < WT_; j += 32) lg[r * WT_ + j] *= inv;
    }
    __syncthreads();

    for (int idx = tid; idx < WT_ * HD_; idx += 256) {
        int i = idx / HD_, dd = idx % HD_;
        float s = 0.f;
        #pragma unroll
        for (int j = 0; j < WT_; j++) s = fmaf(lg[i * WT_ + j], vs[j * HD_ + dd], s);
        out[(size_t)(w * WT_ + i) * C_ + head * HD_ + dd] = s;
    }
}

// ---------------- residual: tokens += windowed proj output ----------------
__global__ void add_windows(float* __restrict__ tokens, const float* __restrict__ src) {
    int idx = blockIdx.x * blockDim.x + threadIdx.x;
    if (idx >= N_ * HW * C_) return;
    int c = idx & (C_ - 1);
    int row = idx >> 7;
    int n = row / HW, p = row % HW;
    int h = p / W_, w = p % W_;
    int t = ((n * NWH_ + h / WS_) * NWW_ + w / WS_) * WT_ + (h % WS_) * WS_ + (w % WS_);
    tokens[idx] += src[(size_t)t * C_ + c];
}

// ---------------- head mean reduce + tiny MLP ----------------
__global__ void zero_head() { if (threadIdx.x < N_ * C_) g_head[threadIdx.x] = 0.f; }

__global__ void head_reduce(const float* __restrict__ tokens) {
    int n = blockIdx.x / (HW / 128);
    int pb = (blockIdx.x % (HW / 128)) * 128;
    int c = threadIdx.x;
    float s = 0.f;
    for (int i = 0; i < 128; i++) s += tokens[((size_t)n * HW + pb + i) * C_ + c];
    atomicAdd(&g_head[n * C_ + c], s);
}

__global__ void head_mlp(const float* __restrict__ r1w, const float* __restrict__ r1b,
                         const float* __restrict__ r2w, const float* __restrict__ r2b,
                         const float* __restrict__ r3w, const float* __restrict__ r3b,
                         float* __restrict__ out) {
    __shared__ float hh[N_ * C_];
    __shared__ float y1[N_ * 256];
    __shared__ float y2[N_ * 256];
    __shared__ float y3[N_ * DOUT_];
    __shared__ float ssum[N_];
    int tid = threadIdx.x;
    if (tid < N_ * C_) hh[tid] = g_head[tid] * (1.f / HW);
    __syncthreads();
    for (int o = tid; o < N_ * 256; o += 256) {
        int n = o >> 8, j = o & 255;
        float s = r1b[j];
        for (int c = 0; c < C_; c++) s = fmaf(hh[n * C_ + c], r1w[j * C_ + c], s);
        y1[o] = s > 0.f ? s : 0.01f * s;
    }
    __syncthreads();
    for (int o = tid; o < N_ * 256; o += 256) {
        int n = o >> 8, j = o & 255;
        float s = r2b[j];
        for (int c = 0; c < 256; c++) s = fmaf(y1[n * 256 + c], r2w[j * 256 + c], s);
        y2[o] = s > 0.f ? s : 0.01f * s;
    }
    __syncthreads();
    for (int o = tid; o < N_ * DOUT_; o += 256) {
        int n = o >> 8, j = o & 255;
        float s = r3b[j];
        for (int c = 0; c < 256; c++) s = fmaf(y2[n * 256 + c], r3w[j * 256 + c], s);
        y3[o] = fmaxf(s, 0.f) + 0.1f;
    }
    __syncthreads();
    if (tid < N_) {
        float s = 0.f;
        for (int j = 0; j < DOUT_; j++) s += y3[tid * DOUT_ + j];
        ssum[tid] = s;
    }
    __syncthreads();
    for (int o = tid; o < N_ * DOUT_; o += 256) {
        int n = o >> 8;
        out[o] = y3[o] / ssum[n];
    }
}

// ---------------- host launch ----------------
static float* symaddr(const void* sym) {
    void* p = nullptr;
    cudaGetSymbolAddress(&p, sym);
    return (float*)p;
}

extern "C" void kernel_launch(void* const* d_in, const int* in_sizes, int n_in,
                              void* d_out, int out_size) {
    const float* x      = (const float*)d_in[0];
    const float* conv_w = (const float*)d_in[1];
    const float* conv_b = (const float*)d_in[2];
    const float* n1_g   = (const float*)d_in[3];
    const float* n1_b   = (const float*)d_in[4];
    const float* qkv_w  = (const float*)d_in[5];
    const float* qkv_b  = (const float*)d_in[6];
    const float* proj_w = (const float*)d_in[7];
    const float* proj_b = (const float*)d_in[8];
    const float* n2_g   = (const float*)d_in[9];
    const float* n2_b   = (const float*)d_in[10];
    const float* fc1_w  = (const float*)d_in[11];
    const float* fc1_b  = (const float*)d_in[12];
    const float* fc2_w  = (const float*)d_in[13];
    const float* fc2_b  = (const float*)d_in[14];
    const float* r1_w   = (const float*)d_in[15];
    const float* r1_b   = (const float*)d_in[16];
    const float* r2_w   = (const float*)d_in[17];
    const float* r2_b   = (const float*)d_in[18];
    const float* r3_w   = (const float*)d_in[19];
    const float* r3_b   = (const float*)d_in[20];
    float* out = (float*)d_out;

    float* xt     = symaddr(g_xt);
    float* tok0   = symaddr(g_tok0);
    float* tokens = symaddr(g_tokens);
    float* hbuf   = symaddr(g_h);
    float* qkvb   = symaddr(g_qkv);
    float* attno  = symaddr(g_attno);
    float* mlp1   = symaddr(g_mlp1);

    // 1) transpose x (n,c,p) -> (n,p,c)
    transpose_ncp<<<dim3(HW / 32, C_ / 32, N_), dim3(32, 8)>>>(x, xt);

    // 2) 1x1 conv as one GEMM; dual-store to tokens and tok0
    gemm_mma<3><<<dim3(1, (N_ * HW) / 128), 256>>>(
        xt, conv_w, conv_b, tokens, tok0, N_ * HW, C_, C_);

    const int mTiles_w = (TOKW_ + 127) / 128;
    const int lnw_blocks = (TOKW_ + 7) / 8;
    const int lnr_blocks = (N_ * HW + 7) / 8;

    for (int d = 0; d < DEPTH_; d++) {
        ln_window<<<lnw_blocks, 256>>>(tokens, n1_g + d * C_, n1_b + d * C_, hbuf);
        gemm_mma<0><<<dim3(3, mTiles_w), 256>>>(
            hbuf, qkv_w + (size_t)d * 3 * C_ * C_, qkv_b + d * 3 * C_,
            qkvb, nullptr, TOKW_, 3 * C_, C_);
        attn_win<<<NWIN_ * HEADS_, 256>>>(qkvb, attno);
        gemm_mma<0><<<dim3(1, mTiles_w), 256>>>(
            attno, proj_w + (size_t)d * C_ * C_, proj_b + d * C_,
            hbuf, nullptr, TOKW_, C_, C_);
        add_windows<<<N_ * HW * C_ / 256, 256>>>(tokens, hbuf);
        ln_rows<<<lnr_blocks, 256>>>(tokens, n2_g + d * C_, n2_b + d * C_, attno, N_ * HW);
        gemm_mma<1><<<dim3(HID_ / 128, (N_ * HW) / 128), 256>>>(
            attno, fc1_w + (size_t)d * HID_ * C_, fc1_b + d * HID_,
            mlp1, nullptr, N_ * HW, HID_, C_);
        gemm_mma<2><<<dim3(1, (N_ * HW) / 128), 256>>>(
            mlp1, fc2_w + (size_t)d * C_ * HID_, fc2_b + d * C_,
            tokens, nullptr, N_ * HW, C_, HID_);
    }

    // head mean + tiny MLP -> y
    zero_head<<<1, 256>>>();
    head_reduce<<<N_ * (HW / 128), 128>>>(tokens);
    head_mlp<<<1, 256>>>(r1_w, r1_b, r2_w, r2_b, r3_w, r3_b, out);

    // maps: out[n,q,p] = queries[n,q,:] . tok0[n,p,:]
    for (int n = 0; n < N_; n++) {
        gemm_mma<0><<<dim3(HW / 128, 1), 256>>>(
            tokens + (size_t)n * HW * C_,
            tok0 + (size_t)n * HW * C_,
            nullptr,
            out + 512 + (size_t)n * NQ_ * HW, nullptr,
            NQ_, HW, C_);
    }
}

// round 4
// speedup vs baseline: 2.0260x; 1.1313x over previous
#include <cuda_runtime.h>
#include <cuda_fp16.h>
#include <cstdint>
#include <math.h>

// ---------------- problem constants ----------------
#define N_     2
#define H_     240
#define W_     320
#define HW     76800
#define C_     128
#define HEADS_ 4
#define HD_    32
#define WS_    7
#define DEPTH_ 4
#define HID_   512
#define NWH_   35
#define NWW_   46
#define NWIN_  (N_*NWH_*NWW_) // 3220
#define WT_    49
#define TOKW_  (NWIN_*WT_)    // 157780
#define NQ_    128
#define DOUT_  256

// weight scratch offsets (halves)
#define WH_CONV 0
#define WH_QKV  16384
#define WH_PROJ (16384+196608)
#define WH_FC1  (16384+196608+65536)
#define WH_FC2  (16384+196608+65536+262144)
#define WH_TOT  (16384+196608+65536+262144+262144)

// ---------------- scratch (device globals) ----------------
__device__ __half g_xth   [(size_t)N_*HW*C_];
__device__ __half g_tok0h [(size_t)N_*HW*C_];
__device__ float  g_tokens[(size_t)N_*HW*C_];
__device__ __half g_hh    [(size_t)TOKW_*C_];    // LN1 out / LN2 out
__device__ __half g_qkvh  [(size_t)TOKW_*3*C_];
__device__ __half g_attnoh[(size_t)TOKW_*C_];
__device__ __half g_mlp1h [(size_t)N_*HW*HID_];
__device__ __half g_wh    [WH_TOT];
__device__ __half g_qh    [N_*NQ_*C_];
__device__ float  g_head  [N_*C_];

// ---------------- helpers ----------------
__device__ __forceinline__ uint32_t smem_u32(const void* p) {
    uint32_t a;
    asm("{ .reg .u64 t; cvta.to.shared.u64 t, %1; cvt.u32.u64 %0, t; }" : "=r"(a) : "l"(p));
    return a;
}
__device__ __forceinline__ float warp_sum(float v) {
    #pragma unroll
    for (int o = 16; o; o >>= 1) v += __shfl_xor_sync(0xffffffffu, v, o);
    return v;
}
__device__ __forceinline__ float warp_max(float v) {
    #pragma unroll
    for (int o = 16; o; o >>= 1) v = fmaxf(v, __shfl_xor_sync(0xffffffffu, v, o));
    return v;
}
__device__ __forceinline__ float gelu_exact(float x) {
    return 0.5f * x * (1.0f + erff(x * 0.70710678118654752f));
}
__device__ __forceinline__ void ldsm_x4(uint32_t& r0, uint32_t& r1, uint32_t& r2, uint32_t& r3,
                                        uint32_t addr) {
    asm volatile("ldmatrix.sync.aligned.m8n8.x4.shared.b16 {%0,%1,%2,%3}, [%4];"
                 : "=r"(r0), "=r"(r1), "=r"(r2), "=r"(r3) : "r"(addr));
}
__device__ __forceinline__ void mma16816(float* c, const uint32_t* a, const uint32_t* b) {
    asm volatile(
        "mma.sync.aligned.m16n8k16.row.col.f32.f16.f16.f32 "
        "{%0,%1,%2,%3}, {%4,%5,%6,%7}, {%8,%9}, {%0,%1,%2,%3};"
        : "+f"(c[0]), "+f"(c[1]), "+f"(c[2]), "+f"(c[3])
        : "r"(a[0]), "r"(a[1]), "r"(a[2]), "r"(a[3]), "r"(b[0]), "r"(b[1]));
}
#define CP16(dst, src) \
    asm volatile("cp.async.cg.shared.global [%0], [%1], 16;" :: "r"(dst), "l"(src))
#define CP_COMMIT() asm volatile("cp.async.commit_group;" ::: "memory")
#define CP_WAIT0()  asm volatile("cp.async.wait_group 0;" ::: "memory")

// ================= fp16 mma.sync GEMM: C[M,N] = A[M,K] . B[N,K]^T (+bias) =================
// EPI: 0 fp32 store, 1 half store, 2 gelu+half store, 3 scatter-add into tokens,
//      4 fp32 accumulate, 5 dual: fp32 store + half store
// Tile 128x128, BK=32 double-buffered via cp.async, 256 threads, warp tile 64x32.
#define RS_ 40          // smem row stride in halves (80B): phase-optimal STS & ldmatrix
#define BUFH_ (128*RS_) // halves per buffer

template <int EPI>
__global__ __launch_bounds__(256)
void gemm_mma(const __half* __restrict__ A, const __half* __restrict__ B,
              const float* __restrict__ bias, float* __restrict__ Cf,
              __half* __restrict__ Ch, int M, int N, int K) {
    __shared__ __align__(16) __half As[2][BUFH_];
    __shared__ __align__(16) __half Bs[2][BUFH_];

    const int tid = threadIdx.x;
    const int wid = tid >> 5, lane = tid & 31;
    const int tileN = blockIdx.x * 128, tileM = blockIdx.y * 128;
    const int wm = (wid >> 2) * 64, wn = (wid & 3) * 32;
    const int rr = lane & 7, gg = lane >> 3;

    const uint32_t sA = smem_u32(As), sB = smem_u32(Bs);
    const int lr = tid >> 2;            // 0..63
    const int lc = (tid & 3) * 8;       // halves offset within 32-half row chunk

    float acc[4][4][4];
    #pragma unroll
    for (int i = 0; i < 4; i++)
        #pragma unroll
        for (int j = 0; j < 4; j++)
            #pragma unroll
            for (int k = 0; k < 4; k++) acc[i][j][k] = 0.f;

    const int KC = K >> 5;

    // loader: each thread covers rows lr and lr+64 for A and B (16B each)
    auto issue = [&](int kc, int buf) {
        int kb = kc * 32 + lc;
        #pragma unroll
        for (int h = 0; h < 2; h++) {
            int r = lr + h * 64;
            uint32_t da = sA + (uint32_t)(buf * BUFH_ + r * RS_ + lc) * 2;
            if (tileM + r < M) CP16(da, A + (size_t)(tileM + r) * K + kb);
            uint32_t db = sB + (uint32_t)(buf * BUFH_ + r * RS_ + lc) * 2;
            if (tileN + r < N) CP16(db, B + (size_t)(tileN + r) * K + kb);
        }
    };

    issue(0, 0);
    CP_COMMIT();

    for (int kc = 0; kc < KC; kc++) {
        const int cur = kc & 1;
        CP_WAIT0();
        __syncthreads();
        if (kc + 1 < KC) { issue(kc + 1, cur ^ 1); CP_COMMIT(); }

        const uint32_t aBase = sA + (uint32_t)(cur * BUFH_) * 2;
        const uint32_t bBase = sB + (uint32_t)(cur * BUFH_) * 2;
        #pragma unroll
        for (int ks = 0; ks < 2; ks++) {
            uint32_t a[4][4];
            #pragma unroll
            for (int mi = 0; mi < 4; mi++) {
                int row = wm + mi * 16 + rr + ((gg & 1) << 3);
                int col = ks * 16 + ((gg >> 1) << 3);
                ldsm_x4(a[mi][0], a[mi][1], a[mi][2], a[mi][3],
                        aBase + (uint32_t)(row * RS_ + col) * 2);
            }
            uint32_t b[2][4];
            #pragma unroll
            for (int p = 0; p < 2; p++) {
                int row = wn + p * 16 + rr + ((gg & 1) << 3);
                int col = ks * 16 + ((gg >> 1) << 3);
                ldsm_x4(b[p][0], b[p][1], b[p][2], b[p][3],
                        bBase + (uint32_t)(row * RS_ + col) * 2);
            }
            #pragma unroll
            for (int mi = 0; mi < 4; mi++) {
                #pragma unroll
                for (int nj = 0; nj < 4; nj++) {
                    int p = nj >> 1;
                    uint32_t bb[2];
                    if (nj & 1) { bb[0] = b[p][1]; bb[1] = b[p][3]; }
                    else        { bb[0] = b[p][0]; bb[1] = b[p][2]; }
                    mma16816(acc[mi][nj], a[mi], bb);
                }
            }
        }
        if (kc + 1 < KC) __syncthreads();
    }

    // epilogue
    const int er = lane >> 2, ec = (lane & 3) * 2;
    #pragma unroll
    for (int mi = 0; mi < 4; mi++) {
        #pragma unroll
        for (int half = 0; half < 2; half++) {
            int gm = tileM + wm + mi * 16 + er + half * 8;
            if (gm >= M) continue;
            #pragma unroll
            for (int nj = 0; nj < 4; nj++) {
                int gn = tileN + wn + nj * 8 + ec;
                float vx = acc[mi][nj][half * 2 + 0];
                float vy = acc[mi][nj][half * 2 + 1];
                if (bias) { vx += bias[gn]; vy += bias[gn + 1]; }
                if (EPI == 2) { vx = gelu_exact(vx); vy = gelu_exact(vy); }
                if (EPI == 1 || EPI == 2) {
                    *(__half2*)(Ch + (size_t)gm * N + gn) = __floats2half2_rn(vx, vy);
                } else if (EPI == 3) {
                    // scatter window token gm -> spatial position; add into tokens
                    int w = gm / WT_, i = gm - w * WT_;
                    int n = w / (NWH_ * NWW_); int rem = w - n * (NWH_ * NWW_);
                    int wh = rem / NWW_, ww = rem - wh * NWW_;
                    int hp = wh * WS_ + i / WS_;
                    int wp = ww * WS_ + i - (i / WS_) * WS_;
                    if (hp < H_ && wp < W_) {
                        size_t o = ((size_t)n * HW + hp * W_ + wp) * C_ + gn;
                        float2 old = *(float2*)(Cf + o);
                        *(float2*)(Cf + o) = make_float2(old.x + vx, old.y + vy);
                    }
                } else if (EPI == 4) {
                    size_t o = (size_t)gm * N + gn;
                    float2 old = *(float2*)(Cf + o);
                    *(float2*)(Cf + o) = make_float2(old.x + vx, old.y + vy);
                } else {
                    size_t o = (size_t)gm * N + gn;
                    *(float2*)(Cf + o) = make_float2(vx, vy);
                    if (EPI == 5)
                        *(__half2*)(Ch + o) = __floats2half2_rn(vx, vy);
                }
            }
        }
    }
}

// ---------------- fp32 -> fp16 convert ----------------
__global__ void cvt_f2h(const float* __restrict__ s, __half* __restrict__ d, int n) {
    int i = blockIdx.x * blockDim.x + threadIdx.x;
    if (i < n) d[i] = __float2half(s[i]);
}

// ---------------- transpose (n,c,p) -> (n,p,c), fp32 -> half ----------------
__global__ void transpose_ncp(const float* __restrict__ in, __half* __restrict__ out) {
    __shared__ float tile[32][33];
    int n = blockIdx.z;
    int p0 = blockIdx.x * 32, c0 = blockIdx.y * 32;
    int x = threadIdx.x, y = threadIdx.y;
    const float* src = in + (size_t)n * C_ * HW;
    #pragma unroll
    for (int yy = y; yy < 32; yy += 8)
        tile[yy][x] = src[(size_t)(c0 + yy) * HW + p0 + x];
    __syncthreads();
    __half* dst = out + (size_t)n * HW * C_;
    #pragma unroll
    for (int yy = y; yy < 32; yy += 8)
        dst[(size_t)(p0 + yy) * C_ + c0 + x] = __float2half(tile[x][yy]);
}

// ---------------- LN over C=128 into padded window layout, half out ----------------
__global__ void ln_window(const float* __restrict__ tokens,
                          const float* __restrict__ g, const float* __restrict__ b,
                          __half* __restrict__ out) {
    int warp = (blockIdx.x * blockDim.x + threadIdx.x) >> 5;
    int lane = threadIdx.x & 31;
    if (warp >= TOKW_) return;
    int w = warp / WT_, i = warp % WT_;
    int n = w / (NWH_ * NWW_); int rem = w % (NWH_ * NWW_);
    int wh = rem / NWW_, ww = rem % NWW_;
    int hp = wh * WS_ + i / WS_;
    int wp = ww * WS_ + i % WS_;
    __half* orow = out + (size_t)warp * C_;
    if (hp < H_ && wp < W_) {
        const float* irow = tokens + ((size_t)n * HW + hp * W_ + wp) * C_;
        float v[4];
        #pragma unroll
        for (int j = 0; j < 4; j++) v[j] = irow[lane + 32 * j];
        float mu = warp_sum(v[0] + v[1] + v[2] + v[3]) * (1.f / C_);
        float vs = 0.f;
        #pragma unroll
        for (int j = 0; j < 4; j++) { float d = v[j] - mu; vs += d * d; }
        vs = warp_sum(vs) * (1.f / C_);
        float rstd = rsqrtf(vs + 1e-5f);
        #pragma unroll
        for (int j = 0; j < 4; j++) {
            int c = lane + 32 * j;
            orow[c] = __float2half((v[j] - mu) * rstd * g[c] + b[c]);
        }
    } else {
        #pragma unroll
        for (int j = 0; j < 4; j++) orow[lane + 32 * j] = __half(0.f);
    }
}

// ---------------- plain LN over rows, half out ----------------
__global__ void ln_rows(const float* __restrict__ in,
                        const float* __restrict__ g, const float* __restrict__ b,
                        __half* __restrict__ out, int rows) {
    int warp = (blockIdx.x * blockDim.x + threadIdx.x) >> 5;
    int lane = threadIdx.x & 31;
    if (warp >= rows) return;
    const float* irow = in + (size_t)warp * C_;
    float v[4];
    #pragma unroll
    for (int j = 0; j < 4; j++) v[j] = irow[lane + 32 * j];
    float mu = warp_sum(v[0] + v[1] + v[2] + v[3]) * (1.f / C_);
    float vs = 0.f;
    #pragma unroll
    for (int j = 0; j < 4; j++) { float d = v[j] - mu; vs += d * d; }
    vs = warp_sum(vs) * (1.f / C_);
    float rstd = rsqrtf(vs + 1e-5f);
    __half* orow = out + (size_t)warp * C_;
    #pragma unroll
    for (int j = 0; j < 4; j++) {
        int c = lane + 32 * j;
        orow[c] = __float2half((v[j] - mu) * rstd * g[c] + b[c]);
    }
}

// ---------------- attention: one block per (window, head), half in/out ----------------
__global__ __launch_bounds__(256)
void attn_win(const __half* __restrict__ qkv, __half* __restrict__ out) {
    __shared__ float qs[WT_ * HD_];
    __shared__ float ks[WT_ * HD_];
    __shared__ float vs[WT_ * HD_];
    __shared__ float lg[WT_ * WT_];
    int w = blockIdx.x >> 2;
    int head = blockIdx.x & 3;
    int tid = threadIdx.x;

    for (int idx = tid; idx < WT_ * HD_; idx += 256) {
        int i = idx / HD_, dd = idx % HD_;
        const __half* base = qkv + (size_t)(w * WT_ + i) * (3 * C_) + head * HD_ + dd;
        qs[idx] = __half2float(base[0]);
        ks[idx] = __half2float(base[C_]);
        vs[idx] = __half2float(base[2 * C_]);
    }
    __syncthreads();

    const float scale = 0.17677669529663687f;
    for (int idx = tid; idx < WT_ * WT_; idx += 256) {
        int i = idx / WT_, j = idx % WT_;
        float s = 0.f;
        #pragma unroll
        for (int d = 0; d < HD_; d++) s = fmaf(qs[i * HD_ + d], ks[j * HD_ + d], s);
        lg[idx] = s * scale;
    }
    __syncthreads();

    int warp = tid >> 5, lane = tid & 31;
    for (int r = warp; r < WT_; r += 8) {
        float m = -1e30f;
        for (int j = lane; j < WT_; j += 32) m = fmaxf(m, lg[r * WT_ + j]);
        m = warp_max(m);
        float s = 0.f;
        for (int j = lane; j < WT_; j += 32) {
            float e = __expf(lg[r * WT_ + j] - m);
            lg[r * WT_ + j] = e;
            s += e;
        }
        s = warp_sum(s);
        float inv = 1.f / s;
        for (int j = lane; j < WT_; j += 32) lg[r * WT_ + j] *= inv;
    }
    __syncthreads();

    for (int idx = tid; idx < WT_ * HD_; idx += 256) {
        int i = idx / HD_, dd = idx % HD_;
        float s = 0.f;
        #pragma unroll
        for (int j = 0; j < WT_; j++) s = fmaf(lg[i * WT_ + j], vs[j * HD_ + dd], s);
        out[(size_t)(w * WT_ + i) * C_ + head * HD_ + dd] = __float2half(s);
    }
}

// ---------------- head mean reduce + tiny MLP ----------------
__global__ void zero_head() { if (threadIdx.x < N_ * C_) g_head[threadIdx.x] = 0.f; }

__global__ void head_reduce(const float* __restrict__ tokens) {
    int n = blockIdx.x / (HW / 128);
    int pb = (blockIdx.x % (HW / 128)) * 128;
    int c = threadIdx.x;
    float s = 0.f;
    for (int i = 0; i < 128; i++) s += tokens[((size_t)n * HW + pb + i) * C_ + c];
    atomicAdd(&g_head[n * C_ + c], s);
}

__global__ void head_mlp(const float* __restrict__ r1w, const float* __restrict__ r1b,
                         const float* __restrict__ r2w, const float* __restrict__ r2b,
                         const float* __restrict__ r3w, const float* __restrict__ r3b,
                         float* __restrict__ out) {
    __shared__ float hh[N_ * C_];
    __shared__ float y1[N_ * 256];
    __shared__ float y2[N_ * 256];
    __shared__ float y3[N_ * DOUT_];
    __shared__ float ssum[N_];
    int tid = threadIdx.x;
    if (tid < N_ * C_) hh[tid] = g_head[tid] * (1.f / HW);
    __syncthreads();
    for (int o = tid; o < N_ * 256; o += 256) {
        int n = o >> 8, j = o & 255;
        float s = r1b[j];
        for (int c = 0; c < C_; c++) s = fmaf(hh[n * C_ + c], r1w[j * C_ + c], s);
        y1[o] = s > 0.f ? s : 0.01f * s;
    }
    __syncthreads();
    for (int o = tid; o < N_ * 256; o += 256) {
        int n = o >> 8, j = o & 255;
        float s = r2b[j];
        for (int c = 0; c < 256; c++) s = fmaf(y1[n * 256 + c], r2w[j * 256 + c], s);
        y2[o] = s > 0.f ? s : 0.01f * s;
    }
    __syncthreads();
    for (int o = tid; o < N_ * DOUT_; o += 256) {
        int n = o >> 8, j = o & 255;
        float s = r3b[j];
        for (int c = 0; c < 256; c++) s = fmaf(y2[n * 256 + c], r3w[j * 256 + c], s);
        y3[o] = fmaxf(s, 0.f) + 0.1f;
    }
    __syncthreads();
    if (tid < N_) {
        float s = 0.f;
        for (int j = 0; j < DOUT_; j++) s += y3[tid * DOUT_ + j];
        ssum[tid] = s;
    }
    __syncthreads();
    for (int o = tid; o < N_ * DOUT_; o += 256) {
        int n = o >> 8;
        out[o] = y3[o] / ssum[n];
    }
}

// ---------------- queries fp32 -> half ----------------
__global__ void cvt_queries(const float* __restrict__ tokens, __half* __restrict__ qh) {
    int i = blockIdx.x * blockDim.x + threadIdx.x;
    if (i < N_ * NQ_ * C_) {
        int n = i / (NQ_ * C_);
        int r = i - n * (NQ_ * C_);
        qh[i] = __float2half(tokens[(size_t)n * HW * C_ + r]);
    }
}

// ---------------- host launch ----------------
static void* symaddr(const void* sym) {
    void* p = nullptr;
    cudaGetSymbolAddress(&p, sym);
    return p;
}

extern "C" void kernel_launch(void* const* d_in, const int* in_sizes, int n_in,
                              void* d_out, int out_size) {
    const float* x      = (const float*)d_in[0];
    const float* conv_w = (const float*)d_in[1];
    const float* conv_b = (const float*)d_in[2];
    const float* n1_g   = (const float*)d_in[3];
    const float* n1_b   = (const float*)d_in[4];
    const float* qkv_w  = (const float*)d_in[5];
    const float* qkv_b  = (const float*)d_in[6];
    const float* proj_w = (const float*)d_in[7];
    const float* proj_b = (const float*)d_in[8];
    const float* n2_g   = (const float*)d_in[9];
    const float* n2_b   = (const float*)d_in[10];
    const float* fc1_w  = (const float*)d_in[11];
    const float* fc1_b  = (const float*)d_in[12];
    const float* fc2_w  = (const float*)d_in[13];
    const float* fc2_b  = (const float*)d_in[14];
    const float* r1_w   = (const float*)d_in[15];
    const float* r1_b   = (const float*)d_in[16];
    const float* r2_w   = (const float*)d_in[17];
    const float* r2_b   = (const float*)d_in[18];
    const float* r3_w   = (const float*)d_in[19];
    const float* r3_b   = (const float*)d_in[20];
    float* out = (float*)d_out;

    __half* xth    = (__half*)symaddr(g_xth);
    __half* tok0h  = (__half*)symaddr(g_tok0h);
    float*  tokens = (float*)symaddr(g_tokens);
    __half* hh     = (__half*)symaddr(g_hh);
    __half* qkvh   = (__half*)symaddr(g_qkvh);
    __half* attnoh = (__half*)symaddr(g_attnoh);
    __half* mlp1h  = (__half*)symaddr(g_mlp1h);
    __half* wh     = (__half*)symaddr(g_wh);
    __half* qh     = (__half*)symaddr(g_qh);

    // weights -> half (once per launch; cheap)
    cvt_f2h<<<(16384 + 255) / 256, 256>>>(conv_w, wh + WH_CONV, 16384);
    cvt_f2h<<<(196608 + 255) / 256, 256>>>(qkv_w, wh + WH_QKV, 196608);
    cvt_f2h<<<(65536 + 255) / 256, 256>>>(proj_w, wh + WH_PROJ, 65536);
    cvt_f2h<<<(262144 + 255) / 256, 256>>>(fc1_w, wh + WH_FC1, 262144);
    cvt_f2h<<<(262144 + 255) / 256, 256>>>(fc2_w, wh + WH_FC2, 262144);

    // transpose x (n,c,p) -> (n,p,c) half
    transpose_ncp<<<dim3(HW / 32, C_ / 32, N_), dim3(32, 8)>>>(x, xth);

    // conv: tokens fp32 + tok0 half
    gemm_mma<5><<<dim3(1, (N_ * HW) / 128), 256>>>(
        xth, wh + WH_CONV, conv_b, tokens, tok0h, N_ * HW, C_, C_);

    const int mTiles_w = (TOKW_ + 127) / 128;
    const int lnw_blocks = (TOKW_ + 7) / 8;
    const int lnr_blocks = (N_ * HW + 7) / 8;

    for (int d = 0; d < DEPTH_; d++) {
        ln_window<<<lnw_blocks, 256>>>(tokens, n1_g + d * C_, n1_b + d * C_, hh);
        gemm_mma<1><<<dim3(3, mTiles_w), 256>>>(
            hh, wh + WH_QKV + (size_t)d * 3 * C_ * C_, qkv_b + d * 3 * C_,
            nullptr, qkvh, TOKW_, 3 * C_, C_);
        attn_win<<<NWIN_ * HEADS_, 256>>>(qkvh, attnoh);
        // proj with fused window->spatial scatter-add into tokens
        gemm_mma<3><<<dim3(1, mTiles_w), 256>>>(
            attnoh, wh + WH_PROJ + (size_t)d * C_ * C_, proj_b + d * C_,
            tokens, nullptr, TOKW_, C_, C_);
        ln_rows<<<lnr_blocks, 256>>>(tokens, n2_g + d * C_, n2_b + d * C_, hh, N_ * HW);
        gemm_mma<2><<<dim3(HID_ / 128, (N_ * HW) / 128), 256>>>(
            hh, wh + WH_FC1 + (size_t)d * HID_ * C_, fc1_b + d * HID_,
            nullptr, mlp1h, N_ * HW, HID_, C_);
        gemm_mma<4><<<dim3(1, (N_ * HW) / 128), 256>>>(
            mlp1h, wh + WH_FC2 + (size_t)d * C_ * HID_, fc2_b + d * C_,
            tokens, nullptr, N_ * HW, C_, HID_);
    }

    // head mean + tiny MLP -> y
    zero_head<<<1, 256>>>();
    head_reduce<<<N_ * (HW / 128), 128>>>(tokens);
    head_mlp<<<1, 256>>>(r1_w, r1_b, r2_w, r2_b, r3_w, r3_b, out);

    // maps: out[n,q,p] = queries[n,q,:] . tok0[n,p,:]
    cvt_queries<<<(N_ * NQ_ * C_ + 255) / 256, 256>>>(tokens, qh);
    for (int n = 0; n < N_; n++) {
        gemm_mma<0><<<dim3(HW / 128, 1), 256>>>(
            qh + (size_t)n * NQ_ * C_,
            tok0h + (size_t)n * HW * C_,
            nullptr,
            out + 512 + (size_t)n * NQ_ * HW, nullptr,
            NQ_, HW, C_);
    }
}

// round 5
// speedup vs baseline: 2.9676x; 1.4648x over previous
#include <cuda_runtime.h>
#include <cuda_fp16.h>
#include <cstdint>
#include <math.h>

// ---------------- problem constants ----------------
#define N_     2
#define H_     240
#define W_     320
#define HW     76800
#define C_     128
#define HEADS_ 4
#define HD_    32
#define WS_    7
#define DEPTH_ 4
#define HID_   512
#define NWH_   35
#define NWW_   46
#define NWIN_  (N_*NWH_*NWW_) // 3220
#define WT_    49
#define TOKW_  (NWIN_*WT_)    // 157780
#define NQ_    128
#define DOUT_  256

// weight scratch offsets (halves)
#define WH_CONV 0
#define WH_QKV  16384
#define WH_PROJ (16384+196608)
#define WH_FC1  (16384+196608+65536)
#define WH_FC2  (16384+196608+65536+262144)
#define WH_TOT  (16384+196608+65536+262144+262144)

// ---------------- scratch (device globals) ----------------
__device__ __half g_xth   [(size_t)N_*HW*C_];
__device__ __half g_tok0h [(size_t)N_*HW*C_];
__device__ float  g_tokens[(size_t)N_*HW*C_];
__device__ __half g_hh    [(size_t)TOKW_*C_];
__device__ __half g_qkvh  [(size_t)TOKW_*3*C_];
__device__ __half g_attnoh[(size_t)TOKW_*C_];
__device__ __half g_mlp1h [(size_t)N_*HW*HID_];
__device__ __half g_wh    [WH_TOT];
__device__ __half g_qh    [N_*NQ_*C_];
__device__ float  g_head  [N_*C_];

// ---------------- helpers ----------------
__device__ __forceinline__ uint32_t smem_u32(const void* p) {
    uint32_t a;
    asm("{ .reg .u64 t; cvta.to.shared.u64 t, %1; cvt.u32.u64 %0, t; }" : "=r"(a) : "l"(p));
    return a;
}
__device__ __forceinline__ float warp_sum(float v) {
    #pragma unroll
    for (int o = 16; o; o >>= 1) v += __shfl_xor_sync(0xffffffffu, v, o);
    return v;
}
__device__ __forceinline__ float warp_max(float v) {
    #pragma unroll
    for (int o = 16; o; o >>= 1) v = fmaxf(v, __shfl_xor_sync(0xffffffffu, v, o));
    return v;
}
__device__ __forceinline__ float gelu_exact(float x) {
    return 0.5f * x * (1.0f + erff(x * 0.70710678118654752f));
}
__device__ __forceinline__ void ldsm_x4(uint32_t& r0, uint32_t& r1, uint32_t& r2, uint32_t& r3,
                                        uint32_t addr) {
    asm volatile("ldmatrix.sync.aligned.m8n8.x4.shared.b16 {%0,%1,%2,%3}, [%4];"
                 : "=r"(r0), "=r"(r1), "=r"(r2), "=r"(r3) : "r"(addr));
}
__device__ __forceinline__ void mma16816(float* c, const uint32_t* a, const uint32_t* b) {
    asm volatile(
        "mma.sync.aligned.m16n8k16.row.col.f32.f16.f16.f32 "
        "{%0,%1,%2,%3}, {%4,%5,%6,%7}, {%8,%9}, {%0,%1,%2,%3};"
        : "+f"(c[0]), "+f"(c[1]), "+f"(c[2]), "+f"(c[3])
        : "r"(a[0]), "r"(a[1]), "r"(a[2]), "r"(a[3]), "r"(b[0]), "r"(b[1]));
}
#define CP16(dst, src) \
    asm volatile("cp.async.cg.shared.global [%0], [%1], 16;" :: "r"(dst), "l"(src))
#define CP_COMMIT() asm volatile("cp.async.commit_group;" ::: "memory")
#define CP_WAIT1()  asm volatile("cp.async.wait_group 1;" ::: "memory")

// ================= fp16 mma.sync GEMM, 3-stage cp.async pipeline =================
// EPI: 0 fp32 store, 1 half store, 2 gelu+half store, 3 scatter-add into tokens,
//      4 fp32 accumulate, 5 dual: fp32 store + half store
#define RS_ 40                       // smem row stride in halves (80B)
#define GSTG_ (128*RS_*2)            // bytes per stage per matrix = 10240
#define GEMM_SMEM (3*GSTG_*2)        // 61440

template <int EPI>
__global__ __launch_bounds__(256)
void gemm_mma(const __half* __restrict__ A, const __half* __restrict__ B,
              const float* __restrict__ bias, float* __restrict__ Cf,
              __half* __restrict__ Ch, int M, int N, int K) {
    extern __shared__ __align__(16) char smem[];
    const uint32_t sS = smem_u32(smem);

    const int tid = threadIdx.x;
    const int wid = tid >> 5, lane = tid & 31;
    const int tileN = blockIdx.x * 128, tileM = blockIdx.y * 128;
    const int wm = (wid >> 2) * 64, wn = (wid & 3) * 32;
    const int rr = lane & 7, gg = lane >> 3;
    const int lr = tid >> 2;
    const int lc = (tid & 3) * 8;

    float acc[4][4][4];
    #pragma unroll
    for (int i = 0; i < 4; i++)
        #pragma unroll
        for (int j = 0; j < 4; j++)
            #pragma unroll
            for (int k = 0; k < 4; k++) acc[i][j][k] = 0.f;

    const int KC = K >> 5;

    auto issue = [&](int kc, int stg) {
        int kb = kc * 32 + lc;
        #pragma unroll
        for (int h = 0; h < 2; h++) {
            int r = lr + h * 64;
            uint32_t da = sS + stg * GSTG_ + (uint32_t)(r * RS_ + lc) * 2;
            if (tileM + r < M) CP16(da, A + (size_t)(tileM + r) * K + kb);
            uint32_t db = sS + 3 * GSTG_ + stg * GSTG_ + (uint32_t)(r * RS_ + lc) * 2;
            if (tileN + r < N) CP16(db, B + (size_t)(tileN + r) * K + kb);
        }
    };

    issue(0, 0); CP_COMMIT();
    if (KC > 1) issue(1, 1);
    CP_COMMIT();

    for (int kc = 0; kc < KC; kc++) {
        CP_WAIT1();
        __syncthreads();
        int pc = kc + 2;
        if (pc < KC) issue(pc, pc - (pc / 3) * 3);
        CP_COMMIT();

        const int stg = kc - (kc / 3) * 3;
        const uint32_t aBase = sS + stg * GSTG_;
        const uint32_t bBase = sS + 3 * GSTG_ + stg * GSTG_;
        #pragma unroll
        for (int ks = 0; ks < 2; ks++) {
            uint32_t a[4][4];
            #pragma unroll
            for (int mi = 0; mi < 4; mi++) {
                int row = wm + mi * 16 + rr + ((gg & 1) << 3);
                int col = ks * 16 + ((gg >> 1) << 3);
                ldsm_x4(a[mi][0], a[mi][1], a[mi][2], a[mi][3],
                        aBase + (uint32_t)(row * RS_ + col) * 2);
            }
            uint32_t b[2][4];
            #pragma unroll
            for (int p = 0; p < 2; p++) {
                int row = wn + p * 16 + rr + ((gg & 1) << 3);
                int col = ks * 16 + ((gg >> 1) << 3);
                ldsm_x4(b[p][0], b[p][1], b[p][2], b[p][3],
                        bBase + (uint32_t)(row * RS_ + col) * 2);
            }
            #pragma unroll
            for (int mi = 0; mi < 4; mi++) {
                #pragma unroll
                for (int nj = 0; nj < 4; nj++) {
                    int p = nj >> 1;
                    uint32_t bb[2];
                    if (nj & 1) { bb[0] = b[p][1]; bb[1] = b[p][3]; }
                    else        { bb[0] = b[p][0]; bb[1] = b[p][2]; }
                    mma16816(acc[mi][nj], a[mi], bb);
                }
            }
        }
    }

    // epilogue
    const int er = lane >> 2, ec = (lane & 3) * 2;
    #pragma unroll
    for (int mi = 0; mi < 4; mi++) {
        #pragma unroll
        for (int half = 0; half < 2; half++) {
            int gm = tileM + wm + mi * 16 + er + half * 8;
            if (gm >= M) continue;
            #pragma unroll
            for (int nj = 0; nj < 4; nj++) {
                int gn = tileN + wn + nj * 8 + ec;
                float vx = acc[mi][nj][half * 2 + 0];
                float vy = acc[mi][nj][half * 2 + 1];
                if (bias) { vx += bias[gn]; vy += bias[gn + 1]; }
                if (EPI == 2) { vx = gelu_exact(vx); vy = gelu_exact(vy); }
                if (EPI == 1 || EPI == 2) {
                    *(__half2*)(Ch + (size_t)gm * N + gn) = __floats2half2_rn(vx, vy);
                } else if (EPI == 3) {
                    int w = gm / WT_, i = gm - w * WT_;
                    int n = w / (NWH_ * NWW_); int rem = w - n * (NWH_ * NWW_);
                    int wh = rem / NWW_, ww = rem - wh * NWW_;
                    int hp = wh * WS_ + i / WS_;
                    int wp = ww * WS_ + i - (i / WS_) * WS_;
                    if (hp < H_ && wp < W_) {
                        size_t o = ((size_t)n * HW + hp * W_ + wp) * C_ + gn;
                        float2 old = *(float2*)(Cf + o);
                        *(float2*)(Cf + o) = make_float2(old.x + vx, old.y + vy);
                    }
                } else if (EPI == 4) {
                    size_t o = (size_t)gm * N + gn;
                    float2 old = *(float2*)(Cf + o);
                    *(float2*)(Cf + o) = make_float2(old.x + vx, old.y + vy);
                } else {
                    size_t o = (size_t)gm * N + gn;
                    *(float2*)(Cf + o) = make_float2(vx, vy);
                    if (EPI == 5)
                        *(__half2*)(Ch + o) = __floats2half2_rn(vx, vy);
                }
            }
        }
    }
}

// ---------------- fp32 -> fp16 convert ----------------
__global__ void cvt_f2h(const float* __restrict__ s, __half* __restrict__ d, int n) {
    int i = blockIdx.x * blockDim.x + threadIdx.x;
    if (i < n) d[i] = __float2half(s[i]);
}

// ---------------- transpose (n,c,p) -> (n,p,c), fp32 -> half ----------------
__global__ void transpose_ncp(const float* __restrict__ in, __half* __restrict__ out) {
    __shared__ float tile[32][33];
    int n = blockIdx.z;
    int p0 = blockIdx.x * 32, c0 = blockIdx.y * 32;
    int x = threadIdx.x, y = threadIdx.y;
    const float* src = in + (size_t)n * C_ * HW;
    #pragma unroll
    for (int yy = y; yy < 32; yy += 8)
        tile[yy][x] = src[(size_t)(c0 + yy) * HW + p0 + x];
    __syncthreads();
    __half* dst = out + (size_t)n * HW * C_;
    #pragma unroll
    for (int yy = y; yy < 32; yy += 8)
        dst[(size_t)(p0 + yy) * C_ + c0 + x] = __float2half(tile[x][yy]);
}

// ---------------- LN over C=128 into padded window layout, half out ----------------
__global__ void ln_window(const float* __restrict__ tokens,
                          const float* __restrict__ g, const float* __restrict__ b,
                          __half* __restrict__ out) {
    int warp = (blockIdx.x * blockDim.x + threadIdx.x) >> 5;
    int lane = threadIdx.x & 31;
    if (warp >= TOKW_) return;
    int w = warp / WT_, i = warp % WT_;
    int n = w / (NWH_ * NWW_); int rem = w % (NWH_ * NWW_);
    int wh = rem / NWW_, ww = rem % NWW_;
    int hp = wh * WS_ + i / WS_;
    int wp = ww * WS_ + i % WS_;
    __half* orow = out + (size_t)warp * C_;
    if (hp < H_ && wp < W_) {
        const float* irow = tokens + ((size_t)n * HW + hp * W_ + wp) * C_;
        float v[4];
        #pragma unroll
        for (int j = 0; j < 4; j++) v[j] = irow[lane + 32 * j];
        float mu = warp_sum(v[0] + v[1] + v[2] + v[3]) * (1.f / C_);
        float vs = 0.f;
        #pragma unroll
        for (int j = 0; j < 4; j++) { float d = v[j] - mu; vs += d * d; }
        vs = warp_sum(vs) * (1.f / C_);
        float rstd = rsqrtf(vs + 1e-5f);
        #pragma unroll
        for (int j = 0; j < 4; j++) {
            int c = lane + 32 * j;
            orow[c] = __float2half((v[j] - mu) * rstd * g[c] + b[c]);
        }
    } else {
        #pragma unroll
        for (int j = 0; j < 4; j++) orow[lane + 32 * j] = __half(0.f);
    }
}

// ---------------- plain LN over rows, half out ----------------
__global__ void ln_rows(const float* __restrict__ in,
                        const float* __restrict__ g, const float* __restrict__ b,
                        __half* __restrict__ out, int rows) {
    int warp = (blockIdx.x * blockDim.x + threadIdx.x) >> 5;
    int lane = threadIdx.x & 31;
    if (warp >= rows) return;
    const float* irow = in + (size_t)warp * C_;
    float v[4];
    #pragma unroll
    for (int j = 0; j < 4; j++) v[j] = irow[lane + 32 * j];
    float mu = warp_sum(v[0] + v[1] + v[2] + v[3]) * (1.f / C_);
    float vs = 0.f;
    #pragma unroll
    for (int j = 0; j < 4; j++) { float d = v[j] - mu; vs += d * d; }
    vs = warp_sum(vs) * (1.f / C_);
    float rstd = rsqrtf(vs + 1e-5f);
    __half* orow = out + (size_t)warp * C_;
    #pragma unroll
    for (int j = 0; j < 4; j++) {
        int c = lane + 32 * j;
        orow[c] = __float2half((v[j] - mu) * rstd * g[c] + b[c]);
    }
}

// ---------------- attention v2: one block per window (4 heads), 4x4 register tiling ----------------
// smem planes: q/k/v [4 heads][52 rows][36 floats], lg [52][52]
#define APR_ 36
#define APLANE_ (52*APR_)            // floats per head-plane
#define AQ_OFF 0
#define AK_OFF (4*APLANE_)
#define AV_OFF (8*APLANE_)
#define ALG_OFF (12*APLANE_)
#define ATTN_SMEM ((12*APLANE_ + 52*52)*4)   // 100672 bytes

__global__ __launch_bounds__(256)
void attn_win(const __half* __restrict__ qkv, __half* __restrict__ out) {
    extern __shared__ __align__(16) float asm_[];
    float* qs = asm_ + AQ_OFF;
    float* ks = asm_ + AK_OFF;
    float* vs = asm_ + AV_OFF;
    float* lg = asm_ + ALG_OFF;

    const int w = blockIdx.x;
    const int tid = threadIdx.x;
    const int warp = tid >> 5, lane = tid & 31;

    // load q/k/v for this window (coalesced over 49x384 halves)
    for (int idx = tid; idx < WT_ * 3 * C_; idx += 256) {
        int r = idx / (3 * C_), c = idx % (3 * C_);
        int t = c >> 7, cc = c & 127;
        int h = cc >> 5, d = cc & 31;
        float v = __half2float(qkv[(size_t)(w * WT_ + r) * (3 * C_) + c]);
        asm_[t * 4 * APLANE_ + h * APLANE_ + r * APR_ + d] = v;
    }
    // zero pad rows 49..51 of k and v (q pad rows produce discarded results)
    for (int idx = tid; idx < 4 * 3 * 32; idx += 256) {
        int h = idx / 96, rem = idx % 96;
        int r = 49 + rem / 32, d = rem % 32;
        ks[h * APLANE_ + r * APR_ + d] = 0.f;
        vs[h * APLANE_ + r * APR_ + d] = 0.f;
    }
    __syncthreads();

    const float scale = 0.17677669529663687f;
    const int ti = tid % 13, tj = tid / 13;   // logits tile coords (tid<169)
    const int pit = tid % 13, pdt = tid / 13; // PV tile coords (tid<104)

    for (int h = 0; h < HEADS_; h++) {
        const float* qp = qs + h * APLANE_;
        const float* kp = ks + h * APLANE_;
        const float* vp = vs + h * APLANE_;

        // ---- logits: 4x4 tiles over 52x52 (valid 49x49) ----
        if (tid < 169) {
            float acc[4][4];
            #pragma unroll
            for (int i = 0; i < 4; i++)
                #pragma unroll
                for (int j = 0; j < 4; j++) acc[i][j] = 0.f;
            #pragma unroll
            for (int dc = 0; dc < 8; dc++) {
                float4 qv[4], kv[4];
                #pragma unroll
                for (int r = 0; r < 4; r++)
                    qv[r] = *(const float4*)(qp + (4 * ti + r) * APR_ + dc * 4);
                #pragma unroll
                for (int c = 0; c < 4; c++)
                    kv[c] = *(const float4*)(kp + (4 * tj + c) * APR_ + dc * 4);
                #pragma unroll
                for (int r = 0; r < 4; r++)
                    #pragma unroll
                    for (int c = 0; c < 4; c++) {
                        acc[r][c] = fmaf(qv[r].x, kv[c].x, acc[r][c]);
                        acc[r][c] = fmaf(qv[r].y, kv[c].y, acc[r][c]);
                        acc[r][c] = fmaf(qv[r].z, kv[c].z, acc[r][c]);
                        acc[r][c] = fmaf(qv[r].w, kv[c].w, acc[r][c]);
                    }
            }
            #pragma unroll
            for (int r = 0; r < 4; r++) {
                int i = 4 * ti + r;
                if (i < WT_) {
                    #pragma unroll
                    for (int c = 0; c < 4; c++)
                        lg[i * 52 + 4 * tj + c] = acc[r][c] * scale;
                }
            }
        }
        __syncthreads();

        // ---- softmax rows (valid cols <49; pad cols -> 0) ----
        for (int r = warp; r < WT_; r += 8) {
            float m = -1e30f;
            for (int j = lane; j < WT_; j += 32) m = fmaxf(m, lg[r * 52 + j]);
            m = warp_max(m);
            float s = 0.f;
            for (int j = lane; j < WT_; j += 32) {
                float e = __expf(lg[r * 52 + j] - m);
                lg[r * 52 + j] = e;
                s += e;
            }
            s = warp_sum(s);
            float inv = 1.f / s;
            for (int j = lane; j < 52; j += 32)
                lg[r * 52 + j] = (j < WT_) ? lg[r * 52 + j] * inv : 0.f;
        }
        __syncthreads();

        // ---- PV: tiles 4 rows x 4 d-cols, loop j in chunks of 4 ----
        if (tid < 104) {
            float acc[4][4];
            #pragma unroll
            for (int i = 0; i < 4; i++)
                #pragma unroll
                for (int j = 0; j < 4; j++) acc[i][j] = 0.f;
            for (int jc = 0; jc < 13; jc++) {
                float4 pv[4], vv[4];
                #pragma unroll
                for (int r = 0; r < 4; r++)
                    pv[r] = *(const float4*)(lg + (4 * pit + r) * 52 + jc * 4);
                #pragma unroll
                for (int jj = 0; jj < 4; jj++)
                    vv[jj] = *(const float4*)(vp + (jc * 4 + jj) * APR_ + pdt * 4);
                #pragma unroll
                for (int r = 0; r < 4; r++) {
                    acc[r][0] = fmaf(pv[r].x, vv[0].x, acc[r][0]);
                    acc[r][1] = fmaf(pv[r].x, vv[0].y, acc[r][1]);
                    acc[r][2] = fmaf(pv[r].x, vv[0].z, acc[r][2]);
                    acc[r][3] = fmaf(pv[r].x, vv[0].w, acc[r][3]);
                    acc[r][0] = fmaf(pv[r].y, vv[1].x, acc[r][0]);
                    acc[r][1] = fmaf(pv[r].y, vv[1].y, acc[r][1]);
                    acc[r][2] = fmaf(pv[r].y, vv[1].z, acc[r][2]);
                    acc[r][3] = fmaf(pv[r].y, vv[1].w, acc[r][3]);
                    acc[r][0] = fmaf(pv[r].z, vv[2].x, acc[r][0]);
                    acc[r][1] = fmaf(pv[r].z, vv[2].y, acc[r][1]);
                    acc[r][2] = fmaf(pv[r].z, vv[2].z, acc[r][2]);
                    acc[r][3] = fmaf(pv[r].z, vv[2].w, acc[r][3]);
                    acc[r][0] = fmaf(pv[r].w, vv[3].x, acc[r][0]);
                    acc[r][1] = fmaf(pv[r].w, vv[3].y, acc[r][1]);
                    acc[r][2] = fmaf(pv[r].w, vv[3].z, acc[r][2]);
                    acc[r][3] = fmaf(pv[r].w, vv[3].w, acc[r][3]);
                }
            }
            #pragma unroll
            for (int r = 0; r < 4; r++) {
                int i = 4 * pit + r;
                if (i < WT_) {
                    #pragma unroll
                    for (int d = 0; d < 4; d++) {
                        out[(size_t)(w * WT_ + i) * C_ + h * HD_ + pdt * 4 + d] =
                            __float2half(acc[r][d]);
                    }
                }
            }
        }
        __syncthreads();
    }
}

// ---------------- head mean reduce + tiny MLP ----------------
__global__ void zero_head() { if (threadIdx.x < N_ * C_) g_head[threadIdx.x] = 0.f; }

__global__ void head_reduce(const float* __restrict__ tokens) {
    int n = blockIdx.x / (HW / 128);
    int pb = (blockIdx.x % (HW / 128)) * 128;
    int c = threadIdx.x;
    float s = 0.f;
    for (int i = 0; i < 128; i++) s += tokens[((size_t)n * HW + pb + i) * C_ + c];
    atomicAdd(&g_head[n * C_ + c], s);
}

__global__ void head_mlp(const float* __restrict__ r1w, const float* __restrict__ r1b,
                         const float* __restrict__ r2w, const float* __restrict__ r2b,
                         const float* __restrict__ r3w, const float* __restrict__ r3b,
                         float* __restrict__ out) {
    __shared__ float hh[N_ * C_];
    __shared__ float y1[N_ * 256];
    __shared__ float y2[N_ * 256];
    __shared__ float y3[N_ * DOUT_];
    __shared__ float ssum[N_];
    int tid = threadIdx.x;
    if (tid < N_ * C_) hh[tid] = g_head[tid] * (1.f / HW);
    __syncthreads();
    for (int o = tid; o < N_ * 256; o += 256) {
        int n = o >> 8, j = o & 255;
        float s = r1b[j];
        for (int c = 0; c < C_; c++) s = fmaf(hh[n * C_ + c], r1w[j * C_ + c], s);
        y1[o] = s > 0.f ? s : 0.01f * s;
    }
    __syncthreads();
    for (int o = tid; o < N_ * 256; o += 256) {
        int n = o >> 8, j = o & 255;
        float s = r2b[j];
        for (int c = 0; c < 256; c++) s = fmaf(y1[n * 256 + c], r2w[j * 256 + c], s);
        y2[o] = s > 0.f ? s : 0.01f * s;
    }
    __syncthreads();
    for (int o = tid; o < N_ * DOUT_; o += 256) {
        int n = o >> 8, j = o & 255;
        float s = r3b[j];
        for (int c = 0; c < 256; c++) s = fmaf(y2[n * 256 + c], r3w[j * 256 + c], s);
        y3[o] = fmaxf(s, 0.f) + 0.1f;
    }
    __syncthreads();
    if (tid < N_) {
        float s = 0.f;
        for (int j = 0; j < DOUT_; j++) s += y3[tid * DOUT_ + j];
        ssum[tid] = s;
    }
    __syncthreads();
    for (int o = tid; o < N_ * DOUT_; o += 256) {
        int n = o >> 8;
        out[o] = y3[o] / ssum[n];
    }
}

// ---------------- queries fp32 -> half ----------------
__global__ void cvt_queries(const float* __restrict__ tokens, __half* __restrict__ qh) {
    int i = blockIdx.x * blockDim.x + threadIdx.x;
    if (i < N_ * NQ_ * C_) {
        int n = i / (NQ_ * C_);
        int r = i - n * (NQ_ * C_);
        qh[i] = __float2half(tokens[(size_t)n * HW * C_ + r]);
    }
}

// ---------------- host launch ----------------
static void* symaddr(const void* sym) {
    void* p = nullptr;
    cudaGetSymbolAddress(&p, sym);
    return p;
}

extern "C" void kernel_launch(void* const* d_in, const int* in_sizes, int n_in,
                              void* d_out, int out_size) {
    const float* x      = (const float*)d_in[0];
    const float* conv_w = (const float*)d_in[1];
    const float* conv_b = (const float*)d_in[2];
    const float* n1_g   = (const float*)d_in[3];
    const float* n1_b   = (const float*)d_in[4];
    const float* qkv_w  = (const float*)d_in[5];
    const float* qkv_b  = (const float*)d_in[6];
    const float* proj_w = (const float*)d_in[7];
    const float* proj_b = (const float*)d_in[8];
    const float* n2_g   = (const float*)d_in[9];
    const float* n2_b   = (const float*)d_in[10];
    const float* fc1_w  = (const float*)d_in[11];
    const float* fc1_b  = (const float*)d_in[12];
    const float* fc2_w  = (const float*)d_in[13];
    const float* fc2_b  = (const float*)d_in[14];
    const float* r1_w   = (const float*)d_in[15];
    const float* r1_b   = (const float*)d_in[16];
    const float* r2_w   = (const float*)d_in[17];
    const float* r2_b   = (const float*)d_in[18];
    const float* r3_w   = (const float*)d_in[19];
    const float* r3_b   = (const float*)d_in[20];
    float* out = (float*)d_out;

    __half* xth    = (__half*)symaddr(g_xth);
    __half* tok0h  = (__half*)symaddr(g_tok0h);
    float*  tokens = (float*)symaddr(g_tokens);
    __half* hh     = (__half*)symaddr(g_hh);
    __half* qkvh   = (__half*)symaddr(g_qkvh);
    __half* attnoh = (__half*)symaddr(g_attnoh);
    __half* mlp1h  = (__half*)symaddr(g_mlp1h);
    __half* wh     = (__half*)symaddr(g_wh);
    __half* qh     = (__half*)symaddr(g_qh);

    cudaFuncSetAttribute(gemm_mma<0>, cudaFuncAttributeMaxDynamicSharedMemorySize, GEMM_SMEM);
    cudaFuncSetAttribute(gemm_mma<1>, cudaFuncAttributeMaxDynamicSharedMemorySize, GEMM_SMEM);
    cudaFuncSetAttribute(gemm_mma<2>, cudaFuncAttributeMaxDynamicSharedMemorySize, GEMM_SMEM);
    cudaFuncSetAttribute(gemm_mma<3>, cudaFuncAttributeMaxDynamicSharedMemorySize, GEMM_SMEM);
    cudaFuncSetAttribute(gemm_mma<4>, cudaFuncAttributeMaxDynamicSharedMemorySize, GEMM_SMEM);
    cudaFuncSetAttribute(gemm_mma<5>, cudaFuncAttributeMaxDynamicSharedMemorySize, GEMM_SMEM);
    cudaFuncSetAttribute(attn_win, cudaFuncAttributeMaxDynamicSharedMemorySize, ATTN_SMEM);

    // weights -> half
    cvt_f2h<<<(16384 + 255) / 256, 256>>>(conv_w, wh + WH_CONV, 16384);
    cvt_f2h<<<(196608 + 255) / 256, 256>>>(qkv_w, wh + WH_QKV, 196608);
    cvt_f2h<<<(65536 + 255) / 256, 256>>>(proj_w, wh + WH_PROJ, 65536);
    cvt_f2h<<<(262144 + 255) / 256, 256>>>(fc1_w, wh + WH_FC1, 262144);
    cvt_f2h<<<(262144 + 255) / 256, 256>>>(fc2_w, wh + WH_FC2, 262144);

    transpose_ncp<<<dim3(HW / 32, C_ / 32, N_), dim3(32, 8)>>>(x, xth);

    gemm_mma<5><<<dim3(1, (N_ * HW) / 128), 256, GEMM_SMEM>>>(
        xth, wh + WH_CONV, conv_b, tokens, tok0h, N_ * HW, C_, C_);

    const int mTiles_w = (TOKW_ + 127) / 128;
    const int lnw_blocks = (TOKW_ + 7) / 8;
    const int lnr_blocks = (N_ * HW + 7) / 8;

    for (int d = 0; d < DEPTH_; d++) {
        ln_window<<<lnw_blocks, 256>>>(tokens, n1_g + d * C_, n1_b + d * C_, hh);
        gemm_mma<1><<<dim3(3, mTiles_w), 256, GEMM_SMEM>>>(
            hh, wh + WH_QKV + (size_t)d * 3 * C_ * C_, qkv_b + d * 3 * C_,
            nullptr, qkvh, TOKW_, 3 * C_, C_);
        attn_win<<<NWIN_, 256, ATTN_SMEM>>>(qkvh, attnoh);
        gemm_mma<3><<<dim3(1, mTiles_w), 256, GEMM_SMEM>>>(
            attnoh, wh + WH_PROJ + (size_t)d * C_ * C_, proj_b + d * C_,
            tokens, nullptr, TOKW_, C_, C_);
        ln_rows<<<lnr_blocks, 256>>>(tokens, n2_g + d * C_, n2_b + d * C_, hh, N_ * HW);
        gemm_mma<2><<<dim3(HID_ / 128, (N_ * HW) / 128), 256, GEMM_SMEM>>>(
            hh, wh + WH_FC1 + (size_t)d * HID_ * C_, fc1_b + d * HID_,
            nullptr, mlp1h, N_ * HW, HID_, C_);
        gemm_mma<4><<<dim3(1, (N_ * HW) / 128), 256, GEMM_SMEM>>>(
            mlp1h, wh + WH_FC2 + (size_t)d * C_ * HID_, fc2_b + d * C_,
            tokens, nullptr, N_ * HW, C_, HID_);
    }

    zero_head<<<1, 256>>>();
    head_reduce<<<N_ * (HW / 128), 128>>>(tokens);
    head_mlp<<<1, 256>>>(r1_w, r1_b, r2_w, r2_b, r3_w, r3_b, out);

    cvt_queries<<<(N_ * NQ_ * C_ + 255) / 256, 256>>>(tokens, qh);
    for (int n = 0; n < N_; n++) {
        gemm_mma<0><<<dim3(HW / 128, 1), 256, GEMM_SMEM>>>(
            qh + (size_t)n * NQ_ * C_,
            tok0h + (size_t)n * HW * C_,
            nullptr,
            out + 512 + (size_t)n * NQ_ * HW, nullptr,
            NQ_, HW, C_);
    }
}

// round 6
// speedup vs baseline: 5.7871x; 1.9501x over previous
#include <cuda_runtime.h>
#include <cuda_fp16.h>
#include <cstdint>
#include <math.h>

// ---------------- problem constants ----------------
#define N_     2
#define H_     240
#define W_     320
#define HW     76800
#define C_     128
#define HEADS_ 4
#define HD_    32
#define WS_    7
#define DEPTH_ 4
#define HID_   512
#define NWH_   35
#define NWW_   46
#define NWIN_  (N_*NWH_*NWW_) // 3220
#define WT_    49
#define TOKW_  (NWIN_*WT_)    // 157780
#define NQ_    128
#define DOUT_  256

// weight scratch offsets (halves)
#define WH_CONV 0
#define WH_QKV  16384
#define WH_PROJ (16384+196608)
#define WH_FC1  (16384+196608+65536)
#define WH_FC2  (16384+196608+65536+262144)
#define WH_TOT  (16384+196608+65536+262144+262144)

// ---------------- scratch (device globals) ----------------
__device__ __half g_xth   [(size_t)N_*HW*C_];
__device__ __half g_tok0h [(size_t)N_*HW*C_];
__device__ float  g_tokens[(size_t)N_*HW*C_];
__device__ __half g_hh    [(size_t)TOKW_*C_];
__device__ __half g_qkvh  [(size_t)TOKW_*3*C_];
__device__ __half g_attnoh[(size_t)TOKW_*C_];
__device__ __half g_mlp1h [(size_t)N_*HW*HID_];
__device__ __half g_wh    [WH_TOT];
__device__ __half g_qh    [N_*NQ_*C_];
__device__ float  g_head  [N_*C_];

// ---------------- helpers ----------------
__device__ __forceinline__ uint32_t smem_u32(const void* p) {
    uint32_t a;
    asm("{ .reg .u64 t; cvta.to.shared.u64 t, %1; cvt.u32.u64 %0, t; }" : "=r"(a) : "l"(p));
    return a;
}
__device__ __forceinline__ float warp_sum(float v) {
    #pragma unroll
    for (int o = 16; o; o >>= 1) v += __shfl_xor_sync(0xffffffffu, v, o);
    return v;
}
__device__ __forceinline__ float gelu_exact(float x) {
    return 0.5f * x * (1.0f + erff(x * 0.70710678118654752f));
}
__device__ __forceinline__ void ldsm_x4(uint32_t& r0, uint32_t& r1, uint32_t& r2, uint32_t& r3,
                                        uint32_t addr) {
    asm volatile("ldmatrix.sync.aligned.m8n8.x4.shared.b16 {%0,%1,%2,%3}, [%4];"
                 : "=r"(r0), "=r"(r1), "=r"(r2), "=r"(r3) : "r"(addr));
}
__device__ __forceinline__ void ldsm_x4t(uint32_t& r0, uint32_t& r1, uint32_t& r2, uint32_t& r3,
                                         uint32_t addr) {
    asm volatile("ldmatrix.sync.aligned.m8n8.x4.trans.shared.b16 {%0,%1,%2,%3}, [%4];"
                 : "=r"(r0), "=r"(r1), "=r"(r2), "=r"(r3) : "r"(addr));
}
__device__ __forceinline__ void mma16816(float* c, const uint32_t* a, const uint32_t* b) {
    asm volatile(
        "mma.sync.aligned.m16n8k16.row.col.f32.f16.f16.f32 "
        "{%0,%1,%2,%3}, {%4,%5,%6,%7}, {%8,%9}, {%0,%1,%2,%3};"
        : "+f"(c[0]), "+f"(c[1]), "+f"(c[2]), "+f"(c[3])
        : "r"(a[0]), "r"(a[1]), "r"(a[2]), "r"(a[3]), "r"(b[0]), "r"(b[1]));
}
#define CP16(dst, src) \
    asm volatile("cp.async.cg.shared.global [%0], [%1], 16;" :: "r"(dst), "l"(src))
#define CP_COMMIT() asm volatile("cp.async.commit_group;" ::: "memory")
#define CP_WAIT1()  asm volatile("cp.async.wait_group 1;" ::: "memory")
#define CP_WAIT0()  asm volatile("cp.async.wait_group 0;" ::: "memory")

// ================= fp16 mma.sync GEMM, 3-stage cp.async pipeline =================
#define RS_ 40
#define GSTG_ (128*RS_*2)
#define GEMM_SMEM (3*GSTG_*2)

template <int EPI>
__global__ __launch_bounds__(256)
void gemm_mma(const __half* __restrict__ A, const __half* __restrict__ B,
              const float* __restrict__ bias, float* __restrict__ Cf,
              __half* __restrict__ Ch, int M, int N, int K) {
    extern __shared__ __align__(16) char smem[];
    const uint32_t sS = smem_u32(smem);

    const int tid = threadIdx.x;
    const int wid = tid >> 5, lane = tid & 31;
    const int tileN = blockIdx.x * 128, tileM = blockIdx.y * 128;
    const int wm = (wid >> 2) * 64, wn = (wid & 3) * 32;
    const int rr = lane & 7, gg = lane >> 3;
    const int lr = tid >> 2;
    const int lc = (tid & 3) * 8;

    float acc[4][4][4];
    #pragma unroll
    for (int i = 0; i < 4; i++)
        #pragma unroll
        for (int j = 0; j < 4; j++)
            #pragma unroll
            for (int k = 0; k < 4; k++) acc[i][j][k] = 0.f;

    const int KC = K >> 5;

    auto issue = [&](int kc, int stg) {
        int kb = kc * 32 + lc;
        #pragma unroll
        for (int h = 0; h < 2; h++) {
            int r = lr + h * 64;
            uint32_t da = sS + stg * GSTG_ + (uint32_t)(r * RS_ + lc) * 2;
            if (tileM + r < M) CP16(da, A + (size_t)(tileM + r) * K + kb);
            uint32_t db = sS + 3 * GSTG_ + stg * GSTG_ + (uint32_t)(r * RS_ + lc) * 2;
            if (tileN + r < N) CP16(db, B + (size_t)(tileN + r) * K + kb);
        }
    };

    issue(0, 0); CP_COMMIT();
    if (KC > 1) issue(1, 1);
    CP_COMMIT();

    for (int kc = 0; kc < KC; kc++) {
        CP_WAIT1();
        __syncthreads();
        int pc = kc + 2;
        if (pc < KC) issue(pc, pc - (pc / 3) * 3);
        CP_COMMIT();

        const int stg = kc - (kc / 3) * 3;
        const uint32_t aBase = sS + stg * GSTG_;
        const uint32_t bBase = sS + 3 * GSTG_ + stg * GSTG_;
        #pragma unroll
        for (int ks = 0; ks < 2; ks++) {
            uint32_t a[4][4];
            #pragma unroll
            for (int mi = 0; mi < 4; mi++) {
                int row = wm + mi * 16 + rr + ((gg & 1) << 3);
                int col = ks * 16 + ((gg >> 1) << 3);
                ldsm_x4(a[mi][0], a[mi][1], a[mi][2], a[mi][3],
                        aBase + (uint32_t)(row * RS_ + col) * 2);
            }
            uint32_t b[2][4];
            #pragma unroll
            for (int p = 0; p < 2; p++) {
                int row = wn + p * 16 + rr + ((gg & 1) << 3);
                int col = ks * 16 + ((gg >> 1) << 3);
                ldsm_x4(b[p][0], b[p][1], b[p][2], b[p][3],
                        bBase + (uint32_t)(row * RS_ + col) * 2);
            }
            #pragma unroll
            for (int mi = 0; mi < 4; mi++) {
                #pragma unroll
                for (int nj = 0; nj < 4; nj++) {
                    int p = nj >> 1;
                    uint32_t bb[2];
                    if (nj & 1) { bb[0] = b[p][1]; bb[1] = b[p][3]; }
                    else        { bb[0] = b[p][0]; bb[1] = b[p][2]; }
                    mma16816(acc[mi][nj], a[mi], bb);
                }
            }
        }
    }

    const int er = lane >> 2, ec = (lane & 3) * 2;
    #pragma unroll
    for (int mi = 0; mi < 4; mi++) {
        #pragma unroll
        for (int half = 0; half < 2; half++) {
            int gm = tileM + wm + mi * 16 + er + half * 8;
            if (gm >= M) continue;
            #pragma unroll
            for (int nj = 0; nj < 4; nj++) {
                int gn = tileN + wn + nj * 8 + ec;
                float vx = acc[mi][nj][half * 2 + 0];
                float vy = acc[mi][nj][half * 2 + 1];
                if (bias) { vx += bias[gn]; vy += bias[gn + 1]; }
                if (EPI == 2) { vx = gelu_exact(vx); vy = gelu_exact(vy); }
                if (EPI == 1 || EPI == 2) {
                    *(__half2*)(Ch + (size_t)gm * N + gn) = __floats2half2_rn(vx, vy);
                } else if (EPI == 3) {
                    int w = gm / WT_, i = gm - w * WT_;
                    int n = w / (NWH_ * NWW_); int rem = w - n * (NWH_ * NWW_);
                    int wh = rem / NWW_, ww = rem - wh * NWW_;
                    int hp = wh * WS_ + i / WS_;
                    int wp = ww * WS_ + i - (i / WS_) * WS_;
                    if (hp < H_ && wp < W_) {
                        size_t o = ((size_t)n * HW + hp * W_ + wp) * C_ + gn;
                        float2 old = *(float2*)(Cf + o);
                        *(float2*)(Cf + o) = make_float2(old.x + vx, old.y + vy);
                    }
                } else if (EPI == 4) {
                    size_t o = (size_t)gm * N + gn;
                    float2 old = *(float2*)(Cf + o);
                    *(float2*)(Cf + o) = make_float2(old.x + vx, old.y + vy);
                } else {
                    size_t o = (size_t)gm * N + gn;
                    *(float2*)(Cf + o) = make_float2(vx, vy);
                    if (EPI == 5)
                        *(__half2*)(Ch + o) = __floats2half2_rn(vx, vy);
                }
            }
        }
    }
}

// ---------------- fp32 -> fp16 convert ----------------
__global__ void cvt_f2h(const float* __restrict__ s, __half* __restrict__ d, int n) {
    int i = blockIdx.x * blockDim.x + threadIdx.x;
    if (i < n) d[i] = __float2half(s[i]);
}

// ---------------- transpose (n,c,p) -> (n,p,c), fp32 -> half ----------------
__global__ void transpose_ncp(const float* __restrict__ in, __half* __restrict__ out) {
    __shared__ float tile[32][33];
    int n = blockIdx.z;
    int p0 = blockIdx.x * 32, c0 = blockIdx.y * 32;
    int x = threadIdx.x, y = threadIdx.y;
    const float* src = in + (size_t)n * C_ * HW;
    #pragma unroll
    for (int yy = y; yy < 32; yy += 8)
        tile[yy][x] = src[(size_t)(c0 + yy) * HW + p0 + x];
    __syncthreads();
    __half* dst = out + (size_t)n * HW * C_;
    #pragma unroll
    for (int yy = y; yy < 32; yy += 8)
        dst[(size_t)(p0 + yy) * C_ + c0 + x] = __float2half(tile[x][yy]);
}

// ---------------- LN over C=128 into padded window layout, half out ----------------
__global__ void ln_window(const float* __restrict__ tokens,
                          const float* __restrict__ g, const float* __restrict__ b,
                          __half* __restrict__ out) {
    int warp = (blockIdx.x * blockDim.x + threadIdx.x) >> 5;
    int lane = threadIdx.x & 31;
    if (warp >= TOKW_) return;
    int w = warp / WT_, i = warp % WT_;
    int n = w / (NWH_ * NWW_); int rem = w % (NWH_ * NWW_);
    int wh = rem / NWW_, ww = rem % NWW_;
    int hp = wh * WS_ + i / WS_;
    int wp = ww * WS_ + i % WS_;
    __half* orow = out + (size_t)warp * C_;
    if (hp < H_ && wp < W_) {
        const float* irow = tokens + ((size_t)n * HW + hp * W_ + wp) * C_;
        float v[4];
        #pragma unroll
        for (int j = 0; j < 4; j++) v[j] = irow[lane + 32 * j];
        float mu = warp_sum(v[0] + v[1] + v[2] + v[3]) * (1.f / C_);
        float vs = 0.f;
        #pragma unroll
        for (int j = 0; j < 4; j++) { float d = v[j] - mu; vs += d * d; }
        vs = warp_sum(vs) * (1.f / C_);
        float rstd = rsqrtf(vs + 1e-5f);
        #pragma unroll
        for (int j = 0; j < 4; j++) {
            int c = lane + 32 * j;
            orow[c] = __float2half((v[j] - mu) * rstd * g[c] + b[c]);
        }
    } else {
        #pragma unroll
        for (int j = 0; j < 4; j++) orow[lane + 32 * j] = __half(0.f);
    }
}

// ---------------- plain LN over rows, half out ----------------
__global__ void ln_rows(const float* __restrict__ in,
                        const float* __restrict__ g, const float* __restrict__ b,
                        __half* __restrict__ out, int rows) {
    int warp = (blockIdx.x * blockDim.x + threadIdx.x) >> 5;
    int lane = threadIdx.x & 31;
    if (warp >= rows) return;
    const float* irow = in + (size_t)warp * C_;
    float v[4];
    #pragma unroll
    for (int j = 0; j < 4; j++) v[j] = irow[lane + 32 * j];
    float mu = warp_sum(v[0] + v[1] + v[2] + v[3]) * (1.f / C_);
    float vs = 0.f;
    #pragma unroll
    for (int j = 0; j < 4; j++) { float d = v[j] - mu; vs += d * d; }
    vs = warp_sum(vs) * (1.f / C_);
    float rstd = rsqrtf(vs + 1e-5f);
    __half* orow = out + (size_t)warp * C_;
    #pragma unroll
    for (int j = 0; j < 4; j++) {
        int c = lane + 32 * j;
        orow[c] = __float2half((v[j] - mu) * rstd * g[c] + b[c]);
    }
}

// ================= attention v3: tensor cores, one warp per head =================
// smem (halves): QKV planes [t(3)][h(4)][64 rows][stride 40]  = 30720 halves
//                P planes   [h(4)][64 rows][stride 72]        = 18432 halves
#define AP_QKV(t, h) (((t)*4 + (h)) * 2560)
#define AP_P(h)      (30720 + (h) * 4608)
#define ATTN_SMEM    ((30720 + 18432) * 2)   // 98304 bytes

__global__ __launch_bounds__(128)
void attn_win(const __half* __restrict__ qkv, __half* __restrict__ out) {
    extern __shared__ __align__(16) __half ash[];
    const int w = blockIdx.x;
    const int tid = threadIdx.x;
    const int wid = tid >> 5, lane = tid & 31;
    const int rr = lane & 7, gg = lane >> 3;
    const int q2 = (lane & 3) * 2;
    const uint32_t sb = smem_u32(ash);

    // load 49 rows x 384 halves into per-head planes via cp.async
    const __half* src = qkv + (size_t)w * WT_ * 384;
    for (int idx = tid; idx < WT_ * 48; idx += 128) {
        int r = idx / 48, u = idx % 48;
        int t = u >> 4, h = (u >> 2) & 3, seg = u & 3;
        uint32_t dst = sb + (uint32_t)((AP_QKV(t, h) + r * 40 + seg * 8)) * 2;
        CP16(dst, src + (size_t)r * 384 + u * 8);
    }
    CP_COMMIT();
    // zero pad rows 49..63 of all 12 planes + P cols 56..63
    uint4 z = make_uint4(0u, 0u, 0u, 0u);
    for (int idx = tid; idx < 900; idx += 128) {
        int plane = idx / 75, rem = idx % 75;
        int r = 49 + rem / 5, seg = rem % 5;
        *(uint4*)((char*)ash + (size_t)(plane * 2560 + r * 40 + seg * 8) * 2) = z;
    }
    for (int idx = tid; idx < 256; idx += 128) {
        int h = idx >> 6, r = idx & 63;
        *(uint4*)((char*)ash + (size_t)(AP_P(h) + r * 72 + 56) * 2) = z;
    }
    CP_WAIT0();
    __syncthreads();

    const int h = wid;
    const uint32_t sQ = sb + (uint32_t)AP_QKV(0, h) * 2;
    const uint32_t sK = sb + (uint32_t)AP_QKV(1, h) * 2;
    const uint32_t sV = sb + (uint32_t)AP_QKV(2, h) * 2;
    const uint32_t sP = sb + (uint32_t)AP_P(h) * 2;
    __half* Pp = ash + AP_P(h);

    // ---- logits S = Q.K^T : 4m x 7n x 2k ----
    float s[4][7][4];
    #pragma unroll
    for (int i = 0; i < 4; i++)
        #pragma unroll
        for (int j = 0; j < 7; j++)
            #pragma unroll
            for (int k = 0; k < 4; k++) s[i][j][k] = 0.f;

    #pragma unroll
    for (int ks = 0; ks < 2; ks++) {
        uint32_t a[4][4];
        #pragma unroll
        for (int mi = 0; mi < 4; mi++)
            ldsm_x4(a[mi][0], a[mi][1], a[mi][2], a[mi][3],
                    sQ + (uint32_t)((mi * 16 + rr + ((gg & 1) << 3)) * 40
                                    + ks * 16 + ((gg >> 1) << 3)) * 2);
        uint32_t b[4][4];
        #pragma unroll
        for (int p = 0; p < 4; p++)
            ldsm_x4(b[p][0], b[p][1], b[p][2], b[p][3],
                    sK + (uint32_t)((p * 16 + rr + ((gg & 1) << 3)) * 40
                                    + ks * 16 + ((gg >> 1) << 3)) * 2);
        #pragma unroll
        for (int mi = 0; mi < 4; mi++)
            #pragma unroll
            for (int nj = 0; nj < 7; nj++) {
                int pg = nj >> 1;
                uint32_t bb[2];
                if (nj & 1) { bb[0] = b[pg][1]; bb[1] = b[pg][3]; }
                else        { bb[0] = b[pg][0]; bb[1] = b[pg][2]; }
                mma16816(s[mi][nj], a[mi], bb);
            }
    }

    // ---- softmax in fragments, write P (half) to smem ----
    const float scale = 0.17677669529663687f;
    #pragma unroll
    for (int mi = 0; mi < 4; mi++) {
        #pragma unroll
        for (int hf = 0; hf < 2; hf++) {
            float mx = -1e30f;
            #pragma unroll
            for (int nj = 0; nj < 7; nj++) {
                int c0 = 8 * nj + q2;
                float v0 = s[mi][nj][hf * 2 + 0];
                float v1 = s[mi][nj][hf * 2 + 1];
                if (c0 < WT_) mx = fmaxf(mx, v0);
                if (c0 + 1 < WT_) mx = fmaxf(mx, v1);
            }
            mx = fmaxf(mx, __shfl_xor_sync(0xffffffffu, mx, 1));
            mx = fmaxf(mx, __shfl_xor_sync(0xffffffffu, mx, 2));
            float p0[7], p1[7], sum = 0.f;
            #pragma unroll
            for (int nj = 0; nj < 7; nj++) {
                int c0 = 8 * nj + q2;
                float v0 = s[mi][nj][hf * 2 + 0];
                float v1 = s[mi][nj][hf * 2 + 1];
                p0[nj] = (c0 < WT_)     ? __expf((v0 - mx) * scale) : 0.f;
                p1[nj] = (c0 + 1 < WT_) ? __expf((v1 - mx) * scale) : 0.f;
                sum += p0[nj] + p1[nj];
            }
            sum += __shfl_xor_sync(0xffffffffu, sum, 1);
            sum += __shfl_xor_sync(0xffffffffu, sum, 2);
            float inv = 1.f / sum;
            int row = mi * 16 + (lane >> 2) + hf * 8;
            #pragma unroll
            for (int nj = 0; nj < 7; nj++)
                *(__half2*)(Pp + row * 72 + 8 * nj + q2) =
                    __floats2half2_rn(p0[nj] * inv, p1[nj] * inv);
        }
    }
    __syncwarp();

    // ---- O = P.V : 4m x 4n x 4k ; V via ldmatrix.trans ----
    float o[4][4][4];
    #pragma unroll
    for (int i = 0; i < 4; i++)
        #pragma unroll
        for (int j = 0; j < 4; j++)
            #pragma unroll
            for (int k = 0; k < 4; k++) o[i][j][k] = 0.f;

    #pragma unroll
    for (int ks = 0; ks < 4; ks++) {
        uint32_t a[4][4];
        #pragma unroll
        for (int mi = 0; mi < 4; mi++)
            ldsm_x4(a[mi][0], a[mi][1], a[mi][2], a[mi][3],
                    sP + (uint32_t)((mi * 16 + rr + ((gg & 1) << 3)) * 72
                                    + ks * 16 + ((gg >> 1) << 3)) * 2);
        uint32_t b[2][4];
        #pragma unroll
        for (int g = 0; g < 2; g++) {
            int row = ks * 16 + rr + ((gg >> 1) << 3);
            int col = g * 16 + ((gg & 1) << 3);
            ldsm_x4t(b[g][0], b[g][1], b[g][2], b[g][3],
                     sV + (uint32_t)(row * 40 + col) * 2);
        }
        #pragma unroll
        for (int mi = 0; mi < 4; mi++)
            #pragma unroll
            for (int nd = 0; nd < 4; nd++) {
                int g = nd >> 1;
                uint32_t bb[2];
                if (nd & 1) { bb[0] = b[g][1]; bb[1] = b[g][3]; }
                else        { bb[0] = b[g][0]; bb[1] = b[g][2]; }
                mma16816(o[mi][nd], a[mi], bb);
            }
    }

    // ---- store ----
    #pragma unroll
    for (int mi = 0; mi < 4; mi++) {
        #pragma unroll
        for (int hf = 0; hf < 2; hf++) {
            int row = mi * 16 + (lane >> 2) + hf * 8;
            if (row < WT_) {
                #pragma unroll
                for (int nd = 0; nd < 4; nd++)
                    *(__half2*)(out + ((size_t)(w * WT_ + row)) * C_ + h * HD_ + 8 * nd + q2) =
                        __floats2half2_rn(o[mi][nd][hf * 2], o[mi][nd][hf * 2 + 1]);
            }
        }
    }
}

// ---------------- head mean reduce + tiny MLP ----------------
__global__ void zero_head() { if (threadIdx.x < N_ * C_) g_head[threadIdx.x] = 0.f; }

__global__ void head_reduce(const float* __restrict__ tokens) {
    int n = blockIdx.x / (HW / 128);
    int pb = (blockIdx.x % (HW / 128)) * 128;
    int c = threadIdx.x;
    float s = 0.f;
    for (int i = 0; i < 128; i++) s += tokens[((size_t)n * HW + pb + i) * C_ + c];
    atomicAdd(&g_head[n * C_ + c], s);
}

__global__ void head_mlp(const float* __restrict__ r1w, const float* __restrict__ r1b,
                         const float* __restrict__ r2w, const float* __restrict__ r2b,
                         const float* __restrict__ r3w, const float* __restrict__ r3b,
                         float* __restrict__ out) {
    __shared__ float hh[N_ * C_];
    __shared__ float y1[N_ * 256];
    __shared__ float y2[N_ * 256];
    __shared__ float y3[N_ * DOUT_];
    __shared__ float ssum[N_];
    int tid = threadIdx.x;
    if (tid < N_ * C_) hh[tid] = g_head[tid] * (1.f / HW);
    __syncthreads();
    for (int o = tid; o < N_ * 256; o += 256) {
        int n = o >> 8, j = o & 255;
        float s = r1b[j];
        for (int c = 0; c < C_; c++) s = fmaf(hh[n * C_ + c], r1w[j * C_ + c], s);
        y1[o] = s > 0.f ? s : 0.01f * s;
    }
    __syncthreads();
    for (int o = tid; o < N_ * 256; o += 256) {
        int n = o >> 8, j = o & 255;
        float s = r2b[j];
        for (int c = 0; c < 256; c++) s = fmaf(y1[n * 256 + c], r2w[j * 256 + c], s);
        y2[o] = s > 0.f ? s : 0.01f * s;
    }
    __syncthreads();
    for (int o = tid; o < N_ * DOUT_; o += 256) {
        int n = o >> 8, j = o & 255;
        float s = r3b[j];
        for (int c = 0; c < 256; c++) s = fmaf(y2[n * 256 + c], r3w[j * 256 + c], s);
        y3[o] = fmaxf(s, 0.f) + 0.1f;
    }
    __syncthreads();
    if (tid < N_) {
        float s = 0.f;
        for (int j = 0; j < DOUT_; j++) s += y3[tid * DOUT_ + j];
        ssum[tid] = s;
    }
    __syncthreads();
    for (int o = tid; o < N_ * DOUT_; o += 256) {
        int n = o >> 8;
        out[o] = y3[o] / ssum[n];
    }
}

// ---------------- queries fp32 -> half ----------------
__global__ void cvt_queries(const float* __restrict__ tokens, __half* __restrict__ qh) {
    int i = blockIdx.x * blockDim.x + threadIdx.x;
    if (i < N_ * NQ_ * C_) {
        int n = i / (NQ_ * C_);
        int r = i - n * (NQ_ * C_);
        qh[i] = __float2half(tokens[(size_t)n * HW * C_ + r]);
    }
}

// ---------------- host launch ----------------
static void* symaddr(const void* sym) {
    void* p = nullptr;
    cudaGetSymbolAddress(&p, sym);
    return p;
}

extern "C" void kernel_launch(void* const* d_in, const int* in_sizes, int n_in,
                              void* d_out, int out_size) {
    const float* x      = (const float*)d_in[0];
    const float* conv_w = (const float*)d_in[1];
    const float* conv_b = (const float*)d_in[2];
    const float* n1_g   = (const float*)d_in[3];
    const float* n1_b   = (const float*)d_in[4];
    const float* qkv_w  = (const float*)d_in[5];
    const float* qkv_b  = (const float*)d_in[6];
    const float* proj_w = (const float*)d_in[7];
    const float* proj_b = (const float*)d_in[8];
    const float* n2_g   = (const float*)d_in[9];
    const float* n2_b   = (const float*)d_in[10];
    const float* fc1_w  = (const float*)d_in[11];
    const float* fc1_b  = (const float*)d_in[12];
    const float* fc2_w  = (const float*)d_in[13];
    const float* fc2_b  = (const float*)d_in[14];
    const float* r1_w   = (const float*)d_in[15];
    const float* r1_b   = (const float*)d_in[16];
    const float* r2_w   = (const float*)d_in[17];
    const float* r2_b   = (const float*)d_in[18];
    const float* r3_w   = (const float*)d_in[19];
    const float* r3_b   = (const float*)d_in[20];
    float* out = (float*)d_out;

    __half* xth    = (__half*)symaddr(g_xth);
    __half* tok0h  = (__half*)symaddr(g_tok0h);
    float*  tokens = (float*)symaddr(g_tokens);
    __half* hh     = (__half*)symaddr(g_hh);
    __half* qkvh   = (__half*)symaddr(g_qkvh);
    __half* attnoh = (__half*)symaddr(g_attnoh);
    __half* mlp1h  = (__half*)symaddr(g_mlp1h);
    __half* wh     = (__half*)symaddr(g_wh);
    __half* qh     = (__half*)symaddr(g_qh);

    cudaFuncSetAttribute(gemm_mma<0>, cudaFuncAttributeMaxDynamicSharedMemorySize, GEMM_SMEM);
    cudaFuncSetAttribute(gemm_mma<1>, cudaFuncAttributeMaxDynamicSharedMemorySize, GEMM_SMEM);
    cudaFuncSetAttribute(gemm_mma<2>, cudaFuncAttributeMaxDynamicSharedMemorySize, GEMM_SMEM);
    cudaFuncSetAttribute(gemm_mma<3>, cudaFuncAttributeMaxDynamicSharedMemorySize, GEMM_SMEM);
    cudaFuncSetAttribute(gemm_mma<4>, cudaFuncAttributeMaxDynamicSharedMemorySize, GEMM_SMEM);
    cudaFuncSetAttribute(gemm_mma<5>, cudaFuncAttributeMaxDynamicSharedMemorySize, GEMM_SMEM);
    cudaFuncSetAttribute(attn_win, cudaFuncAttributeMaxDynamicSharedMemorySize, ATTN_SMEM);

    // weights -> half
    cvt_f2h<<<(16384 + 255) / 256, 256>>>(conv_w, wh + WH_CONV, 16384);
    cvt_f2h<<<(196608 + 255) / 256, 256>>>(qkv_w, wh + WH_QKV, 196608);
    cvt_f2h<<<(65536 + 255) / 256, 256>>>(proj_w, wh + WH_PROJ, 65536);
    cvt_f2h<<<(262144 + 255) / 256, 256>>>(fc1_w, wh + WH_FC1, 262144);
    cvt_f2h<<<(262144 + 255) / 256, 256>>>(fc2_w, wh + WH_FC2, 262144);

    transpose_ncp<<<dim3(HW / 32, C_ / 32, N_), dim3(32, 8)>>>(x, xth);

    gemm_mma<5><<<dim3(1, (N_ * HW) / 128), 256, GEMM_SMEM>>>(
        xth, wh + WH_CONV, conv_b, tokens, tok0h, N_ * HW, C_, C_);

    const int mTiles_w = (TOKW_ + 127) / 128;
    const int lnw_blocks = (TOKW_ + 7) / 8;
    const int lnr_blocks = (N_ * HW + 7) / 8;

    for (int d = 0; d < DEPTH_; d++) {
        ln_window<<<lnw_blocks, 256>>>(tokens, n1_g + d * C_, n1_b + d * C_, hh);
        gemm_mma<1><<<dim3(3, mTiles_w), 256, GEMM_SMEM>>>(
            hh, wh + WH_QKV + (size_t)d * 3 * C_ * C_, qkv_b + d * 3 * C_,
            nullptr, qkvh, TOKW_, 3 * C_, C_);
        attn_win<<<NWIN_, 128, ATTN_SMEM>>>(qkvh, attnoh);
        gemm_mma<3><<<dim3(1, mTiles_w), 256, GEMM_SMEM>>>(
            attnoh, wh + WH_PROJ + (size_t)d * C_ * C_, proj_b + d * C_,
            tokens, nullptr, TOKW_, C_, C_);
        ln_rows<<<lnr_blocks, 256>>>(tokens, n2_g + d * C_, n2_b + d * C_, hh, N_ * HW);
        gemm_mma<2><<<dim3(HID_ / 128, (N_ * HW) / 128), 256, GEMM_SMEM>>>(
            hh, wh + WH_FC1 + (size_t)d * HID_ * C_, fc1_b + d * HID_,
            nullptr, mlp1h, N_ * HW, HID_, C_);
        gemm_mma<4><<<dim3(1, (N_ * HW) / 128), 256, GEMM_SMEM>>>(
            mlp1h, wh + WH_FC2 + (size_t)d * C_ * HID_, fc2_b + d * C_,
            tokens, nullptr, N_ * HW, C_, HID_);
    }

    zero_head<<<1, 256>>>();
    head_reduce<<<N_ * (HW / 128), 128>>>(tokens);
    head_mlp<<<1, 256>>>(r1_w, r1_b, r2_w, r2_b, r3_w, r3_b, out);

    cvt_queries<<<(N_ * NQ_ * C_ + 255) / 256, 256>>>(tokens, qh);
    for (int n = 0; n < N_; n++) {
        gemm_mma<0><<<dim3(HW / 128, 1), 256, GEMM_SMEM>>>(
            qh + (size_t)n * NQ_ * C_,
            tok0h + (size_t)n * HW * C_,
            nullptr,
            out + 512 + (size_t)n * NQ_ * HW, nullptr,
            NQ_, HW, C_);
    }
}

// round 7
// speedup vs baseline: 6.1222x; 1.0579x over previous
#include <cuda_runtime.h>
#include <cuda_fp16.h>
#include <cstdint>
#include <math.h>

// ---------------- problem constants ----------------
#define N_     2
#define H_     240
#define W_     320
#define HW     76800
#define C_     128
#define HEADS_ 4
#define HD_    32
#define WS_    7
#define DEPTH_ 4
#define HID_   512
#define NWH_   35
#define NWW_   46
#define NWIN_  (N_*NWH_*NWW_) // 3220
#define WT_    49
#define TOKW_  (NWIN_*WT_)    // 157780
#define NQ_    128
#define DOUT_  256

// weight scratch offsets (halves)
#define WH_CONV 0
#define WH_QKV  16384
#define WH_PROJ (16384+196608)
#define WH_FC1  (16384+196608+65536)
#define WH_FC2  (16384+196608+65536+262144)
#define WH_TOT  (16384+196608+65536+262144+262144)

// ---------------- scratch (device globals) ----------------
__device__ __half g_xth   [(size_t)N_*HW*C_];
__device__ __half g_tok0h [(size_t)N_*HW*C_];
__device__ float  g_tokens[(size_t)N_*HW*C_];
__device__ __half g_hh    [(size_t)TOKW_*C_];
__device__ __half g_qkvh  [(size_t)TOKW_*3*C_];
__device__ __half g_attnoh[(size_t)TOKW_*C_];
__device__ __half g_mlp1h [(size_t)N_*HW*HID_];
__device__ __half g_wh    [WH_TOT];
__device__ __half g_qh    [N_*NQ_*C_];
__device__ float  g_head  [N_*C_];

// ---------------- helpers ----------------
__device__ __forceinline__ uint32_t smem_u32(const void* p) {
    uint32_t a;
    asm("{ .reg .u64 t; cvta.to.shared.u64 t, %1; cvt.u32.u64 %0, t; }" : "=r"(a) : "l"(p));
    return a;
}
__device__ __forceinline__ float warp_sum(float v) {
    #pragma unroll
    for (int o = 16; o; o >>= 1) v += __shfl_xor_sync(0xffffffffu, v, o);
    return v;
}
__device__ __forceinline__ float gelu_exact(float x) {
    return 0.5f * x * (1.0f + erff(x * 0.70710678118654752f));
}
__device__ __forceinline__ void ldsm_x4(uint32_t& r0, uint32_t& r1, uint32_t& r2, uint32_t& r3,
                                        uint32_t addr) {
    asm volatile("ldmatrix.sync.aligned.m8n8.x4.shared.b16 {%0,%1,%2,%3}, [%4];"
                 : "=r"(r0), "=r"(r1), "=r"(r2), "=r"(r3) : "r"(addr));
}
__device__ __forceinline__ void ldsm_x4t(uint32_t& r0, uint32_t& r1, uint32_t& r2, uint32_t& r3,
                                         uint32_t addr) {
    asm volatile("ldmatrix.sync.aligned.m8n8.x4.trans.shared.b16 {%0,%1,%2,%3}, [%4];"
                 : "=r"(r0), "=r"(r1), "=r"(r2), "=r"(r3) : "r"(addr));
}
__device__ __forceinline__ void mma16816(float* c, const uint32_t* a, const uint32_t* b) {
    asm volatile(
        "mma.sync.aligned.m16n8k16.row.col.f32.f16.f16.f32 "
        "{%0,%1,%2,%3}, {%4,%5,%6,%7}, {%8,%9}, {%0,%1,%2,%3};"
        : "+f"(c[0]), "+f"(c[1]), "+f"(c[2]), "+f"(c[3])
        : "r"(a[0]), "r"(a[1]), "r"(a[2]), "r"(a[3]), "r"(b[0]), "r"(b[1]));
}
#define CP16(dst, src) \
    asm volatile("cp.async.cg.shared.global [%0], [%1], 16;" :: "r"(dst), "l"(src))
#define CP_COMMIT() asm volatile("cp.async.commit_group;" ::: "memory")
#define CP_WAIT0()  asm volatile("cp.async.wait_group 0;" ::: "memory")

// ================= fp16 mma.sync GEMM, 2-stage, K-chunk 64 =================
// EPI: 0 fp32 store, 1 half store, 2 gelu+half store, 3 scatter-add into tokens,
//      4 fp32 accumulate, 5 dual: fp32 store + half store
#define KR_ 72                   // smem row stride in halves (144B), conflict-free
#define STG_ (128*KR_*2)         // bytes per stage per matrix = 18432
#define GEMM_SMEM (4*STG_)       // 73728

template <int EPI>
__global__ __launch_bounds__(256)
void gemm_mma(const __half* __restrict__ A, const __half* __restrict__ B,
              const float* __restrict__ bias, float* __restrict__ Cf,
              __half* __restrict__ Ch, int M, int N, int K) {
    extern __shared__ __align__(16) char smem[];
    const uint32_t sS = smem_u32(smem);

    const int tid = threadIdx.x;
    const int wid = tid >> 5, lane = tid & 31;
    const int tileN = blockIdx.x * 128, tileM = blockIdx.y * 128;
    const int wm = (wid >> 2) * 64, wn = (wid & 3) * 32;
    const int rr = lane & 7, gg = lane >> 3;

    float acc[4][4][4];
    #pragma unroll
    for (int i = 0; i < 4; i++)
        #pragma unroll
        for (int j = 0; j < 4; j++)
            #pragma unroll
            for (int k = 0; k < 4; k++) acc[i][j][k] = 0.f;

    const int KC = K >> 6;

    auto issue = [&](int kc, int stg) {
        int kb = kc * 64;
        #pragma unroll
        for (int q = 0; q < 4; q++) {
            int slot = tid + q * 256;          // 0..1023
            int r = slot >> 3, c8 = (slot & 7) * 8;
            uint32_t da = sS + stg * STG_ + (uint32_t)(r * KR_ + c8) * 2;
            if (tileM + r < M) CP16(da, A + (size_t)(tileM + r) * K + kb + c8);
            uint32_t db = sS + 2 * STG_ + stg * STG_ + (uint32_t)(r * KR_ + c8) * 2;
            if (tileN + r < N) CP16(db, B + (size_t)(tileN + r) * K + kb + c8);
        }
    };

    issue(0, 0); CP_COMMIT();

    for (int kc = 0; kc < KC; kc++) {
        CP_WAIT0();
        __syncthreads();
        if (kc + 1 < KC) { issue(kc + 1, (kc + 1) & 1); CP_COMMIT(); }

        const int stg = kc & 1;
        const uint32_t aBase = sS + stg * STG_;
        const uint32_t bBase = sS + 2 * STG_ + stg * STG_;
        #pragma unroll
        for (int ks = 0; ks < 4; ks++) {
            uint32_t a[4][4];
            #pragma unroll
            for (int mi = 0; mi < 4; mi++) {
                int row = wm + mi * 16 + rr + ((gg & 1) << 3);
                int col = ks * 16 + ((gg >> 1) << 3);
                ldsm_x4(a[mi][0], a[mi][1], a[mi][2], a[mi][3],
                        aBase + (uint32_t)(row * KR_ + col) * 2);
            }
            uint32_t b[2][4];
            #pragma unroll
            for (int p = 0; p < 2; p++) {
                int row = wn + p * 16 + rr + ((gg & 1) << 3);
                int col = ks * 16 + ((gg >> 1) << 3);
                ldsm_x4(b[p][0], b[p][1], b[p][2], b[p][3],
                        bBase + (uint32_t)(row * KR_ + col) * 2);
            }
            #pragma unroll
            for (int mi = 0; mi < 4; mi++) {
                #pragma unroll
                for (int nj = 0; nj < 4; nj++) {
                    int p = nj >> 1;
                    uint32_t bb[2];
                    if (nj & 1) { bb[0] = b[p][1]; bb[1] = b[p][3]; }
                    else        { bb[0] = b[p][0]; bb[1] = b[p][2]; }
                    mma16816(acc[mi][nj], a[mi], bb);
                }
            }
        }
    }

    const int er = lane >> 2, ec = (lane & 3) * 2;
    #pragma unroll
    for (int mi = 0; mi < 4; mi++) {
        #pragma unroll
        for (int half = 0; half < 2; half++) {
            int gm = tileM + wm + mi * 16 + er + half * 8;
            if (gm >= M) continue;
            #pragma unroll
            for (int nj = 0; nj < 4; nj++) {
                int gn = tileN + wn + nj * 8 + ec;
                float vx = acc[mi][nj][half * 2 + 0];
                float vy = acc[mi][nj][half * 2 + 1];
                if (bias) { vx += bias[gn]; vy += bias[gn + 1]; }
                if (EPI == 2) { vx = gelu_exact(vx); vy = gelu_exact(vy); }
                if (EPI == 1 || EPI == 2) {
                    *(__half2*)(Ch + (size_t)gm * N + gn) = __floats2half2_rn(vx, vy);
                } else if (EPI == 3) {
                    int w = gm / WT_, i = gm - w * WT_;
                    int n = w / (NWH_ * NWW_); int rem = w - n * (NWH_ * NWW_);
                    int wh = rem / NWW_, ww = rem - wh * NWW_;
                    int hp = wh * WS_ + i / WS_;
                    int wp = ww * WS_ + i - (i / WS_) * WS_;
                    if (hp < H_ && wp < W_) {
                        size_t o = ((size_t)n * HW + hp * W_ + wp) * C_ + gn;
                        float2 old = *(float2*)(Cf + o);
                        *(float2*)(Cf + o) = make_float2(old.x + vx, old.y + vy);
                    }
                } else if (EPI == 4) {
                    size_t o = (size_t)gm * N + gn;
                    float2 old = *(float2*)(Cf + o);
                    *(float2*)(Cf + o) = make_float2(old.x + vx, old.y + vy);
                } else {
                    size_t o = (size_t)gm * N + gn;
                    *(float2*)(Cf + o) = make_float2(vx, vy);
                    if (EPI == 5)
                        *(__half2*)(Ch + o) = __floats2half2_rn(vx, vy);
                }
            }
        }
    }
}

// ---------------- all weights fp32 -> fp16, one kernel ----------------
__global__ void cvt_weights(const float* __restrict__ cw, const float* __restrict__ qw,
                            const float* __restrict__ pw, const float* __restrict__ f1,
                            const float* __restrict__ f2, __half* __restrict__ wh) {
    int i = blockIdx.x * blockDim.x + threadIdx.x;
    const float* s; int off;
    if (i < WH_QKV)      { s = cw; off = 0; }
    else if (i < WH_PROJ){ s = qw; off = WH_QKV; }
    else if (i < WH_FC1) { s = pw; off = WH_PROJ; }
    else if (i < WH_FC2) { s = f1; off = WH_FC1; }
    else if (i < WH_TOT) { s = f2; off = WH_FC2; }
    else return;
    wh[i] = __float2half(s[i - off]);
}

// ---------------- transpose (n,c,p) -> (n,p,c), fp32 -> half ----------------
__global__ void transpose_ncp(const float* __restrict__ in, __half* __restrict__ out) {
    __shared__ float tile[32][33];
    int n = blockIdx.z;
    int p0 = blockIdx.x * 32, c0 = blockIdx.y * 32;
    int x = threadIdx.x, y = threadIdx.y;
    const float* src = in + (size_t)n * C_ * HW;
    #pragma unroll
    for (int yy = y; yy < 32; yy += 8)
        tile[yy][x] = src[(size_t)(c0 + yy) * HW + p0 + x];
    __syncthreads();
    __half* dst = out + (size_t)n * HW * C_;
    #pragma unroll
    for (int yy = y; yy < 32; yy += 8)
        dst[(size_t)(p0 + yy) * C_ + c0 + x] = __float2half(tile[x][yy]);
}

// ---------------- LN over C=128 into padded window layout, half out ----------------
__global__ void ln_window(const float* __restrict__ tokens,
                          const float* __restrict__ g, const float* __restrict__ b,
                          __half* __restrict__ out) {
    int warp = (blockIdx.x * blockDim.x + threadIdx.x) >> 5;
    int lane = threadIdx.x & 31;
    if (warp >= TOKW_) return;
    int w = warp / WT_, i = warp % WT_;
    int n = w / (NWH_ * NWW_); int rem = w % (NWH_ * NWW_);
    int wh = rem / NWW_, ww = rem % NWW_;
    int hp = wh * WS_ + i / WS_;
    int wp = ww * WS_ + i % WS_;
    __half* orow = out + (size_t)warp * C_;
    if (hp < H_ && wp < W_) {
        const float* irow = tokens + ((size_t)n * HW + hp * W_ + wp) * C_;
        float v[4];
        #pragma unroll
        for (int j = 0; j < 4; j++) v[j] = irow[lane + 32 * j];
        float mu = warp_sum(v[0] + v[1] + v[2] + v[3]) * (1.f / C_);
        float vs = 0.f;
        #pragma unroll
        for (int j = 0; j < 4; j++) { float d = v[j] - mu; vs += d * d; }
        vs = warp_sum(vs) * (1.f / C_);
        float rstd = rsqrtf(vs + 1e-5f);
        #pragma unroll
        for (int j = 0; j < 4; j++) {
            int c = lane + 32 * j;
            orow[c] = __float2half((v[j] - mu) * rstd * g[c] + b[c]);
        }
    } else {
        #pragma unroll
        for (int j = 0; j < 4; j++) orow[lane + 32 * j] = __half(0.f);
    }
}

// ---------------- plain LN over rows, half out ----------------
__global__ void ln_rows(const float* __restrict__ in,
                        const float* __restrict__ g, const float* __restrict__ b,
                        __half* __restrict__ out, int rows) {
    int warp = (blockIdx.x * blockDim.x + threadIdx.x) >> 5;
    int lane = threadIdx.x & 31;
    if (warp >= rows) return;
    const float* irow = in + (size_t)warp * C_;
    float v[4];
    #pragma unroll
    for (int j = 0; j < 4; j++) v[j] = irow[lane + 32 * j];
    float mu = warp_sum(v[0] + v[1] + v[2] + v[3]) * (1.f / C_);
    float vs = 0.f;
    #pragma unroll
    for (int j = 0; j < 4; j++) { float d = v[j] - mu; vs += d * d; }
    vs = warp_sum(vs) * (1.f / C_);
    float rstd = rsqrtf(vs + 1e-5f);
    __half* orow = out + (size_t)warp * C_;
    #pragma unroll
    for (int j = 0; j < 4; j++) {
        int c = lane + 32 * j;
        orow[c] = __float2half((v[j] - mu) * rstd * g[c] + b[c]);
    }
}

// ================= attention: tensor cores, one warp per head, P overlays Q/K =================
// smem (halves): per head h: Q at h*7680, K at h*7680+2560, V at h*7680+5120
//                (each plane 64 rows x stride 40); P overlays Q+K: h*7680, 64 rows x stride 72
#define AP_QKV(t, h) ((h)*7680 + (t)*2560)
#define AP_P(h)      ((h)*7680)
#define ATTN_SMEM    (30720 * 2)   // 61440 bytes

__global__ __launch_bounds__(128)
void attn_win(const __half* __restrict__ qkv, __half* __restrict__ out) {
    extern __shared__ __align__(16) __half ash[];
    const int w = blockIdx.x;
    const int tid = threadIdx.x;
    const int wid = tid >> 5, lane = tid & 31;
    const int rr = lane & 7, gg = lane >> 3;
    const int q2 = (lane & 3) * 2;
    const uint32_t sb = smem_u32(ash);

    // load 49 rows x 384 halves into per-head planes via cp.async
    const __half* src = qkv + (size_t)w * WT_ * 384;
    for (int idx = tid; idx < WT_ * 48; idx += 128) {
        int r = idx / 48, u = idx % 48;
        int t = u >> 4, h = (u >> 2) & 3, seg = u & 3;
        uint32_t dst = sb + (uint32_t)((AP_QKV(t, h) + r * 40 + seg * 8)) * 2;
        CP16(dst, src + (size_t)r * 384 + u * 8);
    }
    CP_COMMIT();
    // zero pad rows 49..63 of all 12 planes
    uint4 z = make_uint4(0u, 0u, 0u, 0u);
    for (int idx = tid; idx < 900; idx += 128) {
        int plane = idx / 75, rem = idx % 75;
        int r = 49 + rem / 5, seg = rem % 5;
        *(uint4*)((char*)ash + (size_t)(plane * 2560 + r * 40 + seg * 8) * 2) = z;
    }
    CP_WAIT0();
    __syncthreads();

    const int h = wid;
    const uint32_t sQ = sb + (uint32_t)AP_QKV(0, h) * 2;
    const uint32_t sK = sb + (uint32_t)AP_QKV(1, h) * 2;
    const uint32_t sV = sb + (uint32_t)AP_QKV(2, h) * 2;
    const uint32_t sP = sb + (uint32_t)AP_P(h) * 2;
    __half* Pp = ash + AP_P(h);

    // ---- logits S = Q.K^T : 4m x 7n x 2k ----
    float s[4][7][4];
    #pragma unroll
    for (int i = 0; i < 4; i++)
        #pragma unroll
        for (int j = 0; j < 7; j++)
            #pragma unroll
            for (int k = 0; k < 4; k++) s[i][j][k] = 0.f;

    #pragma unroll
    for (int ks = 0; ks < 2; ks++) {
        uint32_t a[4][4];
        #pragma unroll
        for (int mi = 0; mi < 4; mi++)
            ldsm_x4(a[mi][0], a[mi][1], a[mi][2], a[mi][3],
                    sQ + (uint32_t)((mi * 16 + rr + ((gg & 1) << 3)) * 40
                                    + ks * 16 + ((gg >> 1) << 3)) * 2);
        uint32_t b[4][4];
        #pragma unroll
        for (int p = 0; p < 4; p++)
            ldsm_x4(b[p][0], b[p][1], b[p][2], b[p][3],
                    sK + (uint32_t)((p * 16 + rr + ((gg & 1) << 3)) * 40
                                    + ks * 16 + ((gg >> 1) << 3)) * 2);
        #pragma unroll
        for (int mi = 0; mi < 4; mi++)
            #pragma unroll
            for (int nj = 0; nj < 7; nj++) {
                int pg = nj >> 1;
                uint32_t bb[2];
                if (nj & 1) { bb[0] = b[pg][1]; bb[1] = b[pg][3]; }
                else        { bb[0] = b[pg][0]; bb[1] = b[pg][2]; }
                mma16816(s[mi][nj], a[mi], bb);
            }
    }
    __syncwarp();   // all Q/K ldsm complete before P overlay writes

    // ---- softmax in fragments, write P (half) to smem (overlay) ----
    const float scale = 0.17677669529663687f;
    #pragma unroll
    for (int mi = 0; mi < 4; mi++) {
        #pragma unroll
        for (int hf = 0; hf < 2; hf++) {
            float mx = -1e30f;
            #pragma unroll
            for (int nj = 0; nj < 7; nj++) {
                int c0 = 8 * nj + q2;
                float v0 = s[mi][nj][hf * 2 + 0];
                float v1 = s[mi][nj][hf * 2 + 1];
                if (c0 < WT_) mx = fmaxf(mx, v0);
                if (c0 + 1 < WT_) mx = fmaxf(mx, v1);
            }
            mx = fmaxf(mx, __shfl_xor_sync(0xffffffffu, mx, 1));
            mx = fmaxf(mx, __shfl_xor_sync(0xffffffffu, mx, 2));
            float p0[7], p1[7], sum = 0.f;
            #pragma unroll
            for (int nj = 0; nj < 7; nj++) {
                int c0 = 8 * nj + q2;
                float v0 = s[mi][nj][hf * 2 + 0];
                float v1 = s[mi][nj][hf * 2 + 1];
                p0[nj] = (c0 < WT_)     ? __expf((v0 - mx) * scale) : 0.f;
                p1[nj] = (c0 + 1 < WT_) ? __expf((v1 - mx) * scale) : 0.f;
                sum += p0[nj] + p1[nj];
            }
            sum += __shfl_xor_sync(0xffffffffu, sum, 1);
            sum += __shfl_xor_sync(0xffffffffu, sum, 2);
            float inv = 1.f / sum;
            int row = mi * 16 + (lane >> 2) + hf * 8;
            #pragma unroll
            for (int nj = 0; nj < 7; nj++)
                *(__half2*)(Pp + row * 72 + 8 * nj + q2) =
                    __floats2half2_rn(p0[nj] * inv, p1[nj] * inv);
        }
    }
    // zero P cols 56..63 (PV k-range covers 64)
    for (int r = lane; r < 64; r += 32)
        *(uint4*)(Pp + r * 72 + 56) = make_uint4(0u, 0u, 0u, 0u);
    __syncwarp();

    // ---- O = P.V : 4m x 4n x 4k ; V via ldmatrix.trans ----
    float o[4][4][4];
    #pragma unroll
    for (int i = 0; i < 4; i++)
        #pragma unroll
        for (int j = 0; j < 4; j++)
            #pragma unroll
            for (int k = 0; k < 4; k++) o[i][j][k] = 0.f;

    #pragma unroll
    for (int ks = 0; ks < 4; ks++) {
        uint32_t a[4][4];
        #pragma unroll
        for (int mi = 0; mi < 4; mi++)
            ldsm_x4(a[mi][0], a[mi][1], a[mi][2], a[mi][3],
                    sP + (uint32_t)((mi * 16 + rr + ((gg & 1) << 3)) * 72
                                    + ks * 16 + ((gg >> 1) << 3)) * 2);
        uint32_t b[2][4];
        #pragma unroll
        for (int g = 0; g < 2; g++) {
            int row = ks * 16 + rr + ((gg >> 1) << 3);
            int col = g * 16 + ((gg & 1) << 3);
            ldsm_x4t(b[g][0], b[g][1], b[g][2], b[g][3],
                     sV + (uint32_t)(row * 40 + col) * 2);
        }
        #pragma unroll
        for (int mi = 0; mi < 4; mi++)
            #pragma unroll
            for (int nd = 0; nd < 4; nd++) {
                int g = nd >> 1;
                uint32_t bb[2];
                if (nd & 1) { bb[0] = b[g][1]; bb[1] = b[g][3]; }
                else        { bb[0] = b[g][0]; bb[1] = b[g][2]; }
                mma16816(o[mi][nd], a[mi], bb);
            }
    }

    // ---- store ----
    #pragma unroll
    for (int mi = 0; mi < 4; mi++) {
        #pragma unroll
        for (int hf = 0; hf < 2; hf++) {
            int row = mi * 16 + (lane >> 2) + hf * 8;
            if (row < WT_) {
                #pragma unroll
                for (int nd = 0; nd < 4; nd++)
                    *(__half2*)(out + ((size_t)(w * WT_ + row)) * C_ + h * HD_ + 8 * nd + q2) =
                        __floats2half2_rn(o[mi][nd][hf * 2], o[mi][nd][hf * 2 + 1]);
            }
        }
    }
}

// ---------------- head mean reduce + tiny MLP ----------------
__global__ void zero_head() { if (threadIdx.x < N_ * C_) g_head[threadIdx.x] = 0.f; }

__global__ void head_reduce(const float* __restrict__ tokens) {
    int n = blockIdx.x / (HW / 128);
    int pb = (blockIdx.x % (HW / 128)) * 128;
    int c = threadIdx.x;
    float s = 0.f;
    for (int i = 0; i < 128; i++) s += tokens[((size_t)n * HW + pb + i) * C_ + c];
    atomicAdd(&g_head[n * C_ + c], s);
}

__global__ void head_mlp(const float* __restrict__ r1w, const float* __restrict__ r1b,
                         const float* __restrict__ r2w, const float* __restrict__ r2b,
                         const float* __restrict__ r3w, const float* __restrict__ r3b,
                         float* __restrict__ out) {
    __shared__ float hh[N_ * C_];
    __shared__ float y1[N_ * 256];
    __shared__ float y2[N_ * 256];
    __shared__ float y3[N_ * DOUT_];
    __shared__ float ssum[N_];
    int tid = threadIdx.x;
    if (tid < N_ * C_) hh[tid] = g_head[tid] * (1.f / HW);
    __syncthreads();
    for (int o = tid; o < N_ * 256; o += 256) {
        int n = o >> 8, j = o & 255;
        float s = r1b[j];
        for (int c = 0; c < C_; c++) s = fmaf(hh[n * C_ + c], r1w[j * C_ + c], s);
        y1[o] = s > 0.f ? s : 0.01f * s;
    }
    __syncthreads();
    for (int o = tid; o < N_ * 256; o += 256) {
        int n = o >> 8, j = o & 255;
        float s = r2b[j];
        for (int c = 0; c < 256; c++) s = fmaf(y1[n * 256 + c], r2w[j * 256 + c], s);
        y2[o] = s > 0.f ? s : 0.01f * s;
    }
    __syncthreads();
    for (int o = tid; o < N_ * DOUT_; o += 256) {
        int n = o >> 8, j = o & 255;
        float s = r3b[j];
        for (int c = 0; c < 256; c++) s = fmaf(y2[n * 256 + c], r3w[j * 256 + c], s);
        y3[o] = fmaxf(s, 0.f) + 0.1f;
    }
    __syncthreads();
    if (tid < N_) {
        float s = 0.f;
        for (int j = 0; j < DOUT_; j++) s += y3[tid * DOUT_ + j];
        ssum[tid] = s;
    }
    __syncthreads();
    for (int o = tid; o < N_ * DOUT_; o += 256) {
        int n = o >> 8;
        out[o] = y3[o] / ssum[n];
    }
}

// ---------------- queries fp32 -> half ----------------
__global__ void cvt_queries(const float* __restrict__ tokens, __half* __restrict__ qh) {
    int i = blockIdx.x * blockDim.x + threadIdx.x;
    if (i < N_ * NQ_ * C_) {
        int n = i / (NQ_ * C_);
        int r = i - n * (NQ_ * C_);
        qh[i] = __float2half(tokens[(size_t)n * HW * C_ + r]);
    }
}

// ---------------- host launch ----------------
static void* symaddr(const void* sym) {
    void* p = nullptr;
    cudaGetSymbolAddress(&p, sym);
    return p;
}

extern "C" void kernel_launch(void* const* d_in, const int* in_sizes, int n_in,
                              void* d_out, int out_size) {
    const float* x      = (const float*)d_in[0];
    const float* conv_w = (const float*)d_in[1];
    const float* conv_b = (const float*)d_in[2];
    const float* n1_g   = (const float*)d_in[3];
    const float* n1_b   = (const float*)d_in[4];
    const float* qkv_w  = (const float*)d_in[5];
    const float* qkv_b  = (const float*)d_in[6];
    const float* proj_w = (const float*)d_in[7];
    const float* proj_b = (const float*)d_in[8];
    const float* n2_g   = (const float*)d_in[9];
    const float* n2_b   = (const float*)d_in[10];
    const float* fc1_w  = (const float*)d_in[11];
    const float* fc1_b  = (const float*)d_in[12];
    const float* fc2_w  = (const float*)d_in[13];
    const float* fc2_b  = (const float*)d_in[14];
    const float* r1_w   = (const float*)d_in[15];
    const float* r1_b   = (const float*)d_in[16];
    const float* r2_w   = (const float*)d_in[17];
    const float* r2_b   = (const float*)d_in[18];
    const float* r3_w   = (const float*)d_in[19];
    const float* r3_b   = (const float*)d_in[20];
    float* out = (float*)d_out;

    __half* xth    = (__half*)symaddr(g_xth);
    __half* tok0h  = (__half*)symaddr(g_tok0h);
    float*  tokens = (float*)symaddr(g_tokens);
    __half* hh     = (__half*)symaddr(g_hh);
    __half* qkvh   = (__half*)symaddr(g_qkvh);
    __half* attnoh = (__half*)symaddr(g_attnoh);
    __half* mlp1h  = (__half*)symaddr(g_mlp1h);
    __half* wh     = (__half*)symaddr(g_wh);
    __half* qh     = (__half*)symaddr(g_qh);

    cudaFuncSetAttribute(gemm_mma<0>, cudaFuncAttributeMaxDynamicSharedMemorySize, GEMM_SMEM);
    cudaFuncSetAttribute(gemm_mma<1>, cudaFuncAttributeMaxDynamicSharedMemorySize, GEMM_SMEM);
    cudaFuncSetAttribute(gemm_mma<2>, cudaFuncAttributeMaxDynamicSharedMemorySize, GEMM_SMEM);
    cudaFuncSetAttribute(gemm_mma<3>, cudaFuncAttributeMaxDynamicSharedMemorySize, GEMM_SMEM);
    cudaFuncSetAttribute(gemm_mma<4>, cudaFuncAttributeMaxDynamicSharedMemorySize, GEMM_SMEM);
    cudaFuncSetAttribute(gemm_mma<5>, cudaFuncAttributeMaxDynamicSharedMemorySize, GEMM_SMEM);
    cudaFuncSetAttribute(attn_win, cudaFuncAttributeMaxDynamicSharedMemorySize, ATTN_SMEM);

    cvt_weights<<<(WH_TOT + 255) / 256, 256>>>(conv_w, qkv_w, proj_w, fc1_w, fc2_w, wh);

    transpose_ncp<<<dim3(HW / 32, C_ / 32, N_), dim3(32, 8)>>>(x, xth);

    gemm_mma<5><<<dim3(1, (N_ * HW) / 128), 256, GEMM_SMEM>>>(
        xth, wh + WH_CONV, conv_b, tokens, tok0h, N_ * HW, C_, C_);

    const int mTiles_w = (TOKW_ + 127) / 128;
    const int lnw_blocks = (TOKW_ + 7) / 8;
    const int lnr_blocks = (N_ * HW + 7) / 8;

    for (int d = 0; d < DEPTH_; d++) {
        ln_window<<<lnw_blocks, 256>>>(tokens, n1_g + d * C_, n1_b + d * C_, hh);
        gemm_mma<1><<<dim3(3, mTiles_w), 256, GEMM_SMEM>>>(
            hh, wh + WH_QKV + (size_t)d * 3 * C_ * C_, qkv_b + d * 3 * C_,
            nullptr, qkvh, TOKW_, 3 * C_, C_);
        attn_win<<<NWIN_, 128, ATTN_SMEM>>>(qkvh, attnoh);
        gemm_mma<3><<<dim3(1, mTiles_w), 256, GEMM_SMEM>>>(
            attnoh, wh + WH_PROJ + (size_t)d * C_ * C_, proj_b + d * C_,
            tokens, nullptr, TOKW_, C_, C_);
        ln_rows<<<lnr_blocks, 256>>>(tokens, n2_g + d * C_, n2_b + d * C_, hh, N_ * HW);
        gemm_mma<2><<<dim3(HID_ / 128, (N_ * HW) / 128), 256, GEMM_SMEM>>>(
            hh, wh + WH_FC1 + (size_t)d * HID_ * C_, fc1_b + d * HID_,
            nullptr, mlp1h, N_ * HW, HID_, C_);
        gemm_mma<4><<<dim3(1, (N_ * HW) / 128), 256, GEMM_SMEM>>>(
            mlp1h, wh + WH_FC2 + (size_t)d * C_ * HID_, fc2_b + d * C_,
            tokens, nullptr, N_ * HW, C_, HID_);
    }

    zero_head<<<1, 256>>>();
    head_reduce<<<N_ * (HW / 128), 128>>>(tokens);
    head_mlp<<<1, 256>>>(r1_w, r1_b, r2_w, r2_b, r3_w, r3_b, out);

    cvt_queries<<<(N_ * NQ_ * C_ + 255) / 256, 256>>>(tokens, qh);
    for (int n = 0; n < N_; n++) {
        gemm_mma<0><<<dim3(HW / 128, 1), 256, GEMM_SMEM>>>(
            qh + (size_t)n * NQ_ * C_,
            tok0h + (size_t)n * HW * C_,
            nullptr,
            out + 512 + (size_t)n * NQ_ * HW, nullptr,
            NQ_, HW, C_);
    }
}